// round 3
// baseline (speedup 1.0000x reference)
#include <cuda_runtime.h>
#include <math.h>

typedef unsigned long long u64;

// ---------------- model constants ----------------
constexpr int Dm  = 768;
constexpr int DIm = 1536;
constexpr int Nst = 16;
constexpr int Rr  = 48;
constexpr int NLs = 8;
constexpr int Bb  = 2;
constexpr int Ll  = 1024;
constexpr int Mrows = Bb * Ll;          // 2048
constexpr float EPSf = 1e-5f;

// ---------------- scratch (static device memory; no allocations) ----------------
constexpr size_t OFF_RES = 0;
constexpr size_t OFF_H   = OFF_RES + (size_t)Mrows * Dm;
constexpr size_t OFF_X   = OFF_H   + (size_t)Mrows * Dm;
constexpr size_t OFF_XZ  = OFF_X   + (size_t)Mrows * Dm;
constexpr size_t OFF_XC  = OFF_XZ  + (size_t)Mrows * 2 * DIm;
constexpr size_t OFF_DT  = OFF_XC  + (size_t)Mrows * DIm;
constexpr size_t OFF_Y   = OFF_DT  + (size_t)Mrows * DIm;
constexpr size_t OFF_DBL = OFF_Y   + (size_t)Mrows * DIm;
constexpr size_t SCRATCH_TOTAL = OFF_DBL + (size_t)Mrows * 80;

__device__ float g_scratch[SCRATCH_TOTAL];

// ---------------- packed f32x2 helpers ----------------
__device__ __forceinline__ void ffma2(u64& c, u64 a, u64 b)
{
    asm("fma.rn.f32x2 %0, %1, %2, %0;" : "+l"(c) : "l"(a), "l"(b));
}
__device__ __forceinline__ void unpack2(u64 v, float& lo, float& hi)
{
    asm("mov.b64 {%0, %1}, %2;" : "=f"(lo), "=f"(hi) : "l"(v));
}

// ---------------- embedding gather ----------------
__global__ void embed_kernel(const int* __restrict__ ids,
                             const float* __restrict__ emb,
                             float* __restrict__ res)
{
    int idx = blockIdx.x * blockDim.x + threadIdx.x;
    if (idx >= Mrows * Dm) return;
    int row = idx / Dm;
    int c   = idx - row * Dm;
    res[idx] = emb[(size_t)ids[row] * Dm + c];
}

// ---------------- residual add + RMSNorm ----------------
__global__ void rms_resid_kernel(float* __restrict__ res,
                                 const float* __restrict__ xadd,
                                 const float* __restrict__ w,
                                 float* __restrict__ out,
                                 int addx)
{
    const int row = blockIdx.x;
    const int tid = threadIdx.x;          // 256 threads, D=768 -> 3 elems each
    float v[3];
    float local = 0.f;
#pragma unroll
    for (int j = 0; j < 3; j++) {
        int c = tid + j * 256;
        float t = res[(size_t)row * Dm + c];
        if (addx) {
            t += xadd[(size_t)row * Dm + c];
            res[(size_t)row * Dm + c] = t;
        }
        v[j] = t;
        local += t * t;
    }
#pragma unroll
    for (int o = 16; o > 0; o >>= 1) local += __shfl_xor_sync(0xffffffffu, local, o);
    __shared__ float warpsum[8];
    __shared__ float sscale;
    if ((tid & 31) == 0) warpsum[tid >> 5] = local;
    __syncthreads();
    if (tid == 0) {
        float t = 0.f;
#pragma unroll
        for (int j = 0; j < 8; j++) t += warpsum[j];
        sscale = rsqrtf(t / (float)Dm + EPSf);
    }
    __syncthreads();
    float sc = sscale;
#pragma unroll
    for (int j = 0; j < 3; j++) {
        int c = tid + j * 256;
        out[(size_t)row * Dm + c] = v[j] * sc * w[c];
    }
}

// ============================================================================
// High-throughput fp32 GEMM with packed f32x2 FMA (FFMA2).
// C[M,N] = A[M,K](lda) @ W[N,K]^T.  BM=128 fixed, BN template (128 or 64).
// 256 threads, per-thread 8 x TN microtile held as f32x2 pairs.
// A tile is stored DUPLICATED in smem so the broadcast a-pair is one LDS.64.
// Requires: M % 128 == 0, N % BN == 0, K % 8 == 0, lda % 4 == 0.
// EPI 0: plain store   EPI 1: softplus(acc + bias[n])
// ============================================================================
template <int BN, int EPI>
__global__ __launch_bounds__(256, 2)
void sgemm_tn(const float* __restrict__ A, int lda,
              const float* __restrict__ W,
              float* __restrict__ C, int ldc,
              int K, const float* __restrict__ bias)
{
    constexpr int TN  = BN / 16;   // cols per thread: 8 or 4
    constexpr int NP2 = TN / 2;    // f32x2 pairs per thread: 4 or 2

    __shared__ float As[2][8][258];       // duplicated pairs: [k][2*row+{0,1}]
    __shared__ float Ws[2][8][BN + 2];

    const int bm = blockIdx.y * 128;
    const int bn = blockIdx.x * BN;
    const int t  = threadIdx.x;

    // --- A loader: 128 rows x 8 k, one float4 per thread ---
    const int arow = t >> 1;
    const int ak   = (t & 1) * 4;
    const float* Ap = A + (size_t)(bm + arow) * lda + ak;

    // --- W loader ---
    int wrow, wk;
    if (BN == 128) { wrow = t >> 1; wk = (t & 1) * 4; }
    else           { wrow = t >> 2; wk = (t & 3) * 2; }
    const float* Wp = W + (size_t)(bn + wrow) * K + wk;

    const int ty = t >> 4;   // 0..15 (row group)
    const int tx = t & 15;   // 0..15 (col group)

    u64 acc[8][NP2];
#pragma unroll
    for (int i = 0; i < 8; i++)
#pragma unroll
        for (int j = 0; j < NP2; j++) acc[i][j] = 0ull;

    const int ntiles = K >> 3;

    // ---- prologue: tile 0 ----
    {
        float4 av = *(const float4*)Ap;
#pragma unroll
        for (int j = 0; j < 4; j++) {
            float v = ((const float*)&av)[j];
            *(float2*)&As[0][ak + j][2 * arow] = make_float2(v, v);
        }
        if (BN == 128) {
            float4 wv = *(const float4*)Wp;
#pragma unroll
            for (int j = 0; j < 4; j++)
                Ws[0][wk + j][wrow] = ((const float*)&wv)[j];
        } else {
            float2 wv = *(const float2*)Wp;
            Ws[0][wk + 0][wrow] = wv.x;
            Ws[0][wk + 1][wrow] = wv.y;
        }
    }
    __syncthreads();

    for (int tile = 0; tile < ntiles; ++tile) {
        const int buf = tile & 1;
        const bool more = (tile + 1 < ntiles);
        float4 av2;
        float4 wv4;
        float2 wv2;
        if (more) {
            av2 = *(const float4*)(Ap + (size_t)(tile + 1) * 8);
            if (BN == 128) wv4 = *(const float4*)(Wp + (size_t)(tile + 1) * 8);
            else           wv2 = *(const float2*)(Wp + (size_t)(tile + 1) * 8);
        }

#pragma unroll
        for (int k = 0; k < 8; ++k) {
            u64 a2[8], bp[NP2];
#pragma unroll
            for (int i = 0; i < 8; ++i)
                a2[i] = *(const u64*)&As[buf][k][(ty * 8 + i) * 2];
#pragma unroll
            for (int j = 0; j < NP2; ++j)
                bp[j] = *(const u64*)&Ws[buf][k][tx * TN + 2 * j];
#pragma unroll
            for (int i = 0; i < 8; ++i)
#pragma unroll
                for (int j = 0; j < NP2; ++j)
                    ffma2(acc[i][j], a2[i], bp[j]);
        }

        if (more) {
            const int nb = buf ^ 1;
#pragma unroll
            for (int j = 0; j < 4; j++) {
                float v = ((const float*)&av2)[j];
                *(float2*)&As[nb][ak + j][2 * arow] = make_float2(v, v);
            }
            if (BN == 128) {
#pragma unroll
                for (int j = 0; j < 4; j++)
                    Ws[nb][wk + j][wrow] = ((const float*)&wv4)[j];
            } else {
                Ws[nb][wk + 0][wrow] = wv2.x;
                Ws[nb][wk + 1][wrow] = wv2.y;
            }
        }
        __syncthreads();
    }

    // ---- epilogue ----
#pragma unroll
    for (int i = 0; i < 8; ++i) {
        const int row = bm + ty * 8 + i;
#pragma unroll
        for (int j = 0; j < NP2; ++j) {
            const int col = bn + tx * TN + 2 * j;
            float lo, hi;
            unpack2(acc[i][j], lo, hi);
            if (EPI == 1) {
                lo += bias[col];
                hi += bias[col + 1];
                lo = (lo > 20.f) ? lo : log1pf(expf(lo));
                hi = (hi > 20.f) ? hi : log1pf(expf(hi));
            }
            *(float2*)&C[(size_t)row * ldc + col] = make_float2(lo, hi);
        }
    }
}

// ---------------- small GEMM (64x64 tile) for x_proj (N=80) ----------------
template <int EPI>
__global__ void gemm_atb(const float* __restrict__ A, int lda,
                         const float* __restrict__ W,
                         float* __restrict__ C, int ldc,
                         int M, int N, int K,
                         const float* __restrict__ bias)
{
    __shared__ float As[16][68];
    __shared__ float Ws[16][68];
    const int bm = blockIdx.y * 64;
    const int bn = blockIdx.x * 64;
    const int tid = threadIdx.x;
    const int r0 = (tid >> 4) << 2;
    const int c0 = (tid & 15) << 2;
    float acc[4][4] = {};

    for (int k0 = 0; k0 < K; k0 += 16) {
#pragma unroll
        for (int i = 0; i < 4; i++) {
            int idx = tid + i * 256;
            int m = idx >> 4, k = idx & 15;
            int gm = bm + m;
            As[k][m] = (gm < M) ? A[(size_t)gm * lda + k0 + k] : 0.f;
            int gn = bn + m;
            Ws[k][m] = (gn < N) ? W[(size_t)gn * K + k0 + k] : 0.f;
        }
        __syncthreads();
#pragma unroll
        for (int k = 0; k < 16; k++) {
            float a0 = As[k][r0 + 0], a1 = As[k][r0 + 1], a2 = As[k][r0 + 2], a3 = As[k][r0 + 3];
            float b0 = Ws[k][c0 + 0], b1 = Ws[k][c0 + 1], b2 = Ws[k][c0 + 2], b3 = Ws[k][c0 + 3];
            acc[0][0] += a0 * b0; acc[0][1] += a0 * b1; acc[0][2] += a0 * b2; acc[0][3] += a0 * b3;
            acc[1][0] += a1 * b0; acc[1][1] += a1 * b1; acc[1][2] += a1 * b2; acc[1][3] += a1 * b3;
            acc[2][0] += a2 * b0; acc[2][1] += a2 * b1; acc[2][2] += a2 * b2; acc[2][3] += a2 * b3;
            acc[3][0] += a3 * b0; acc[3][1] += a3 * b1; acc[3][2] += a3 * b2; acc[3][3] += a3 * b3;
        }
        __syncthreads();
    }

#pragma unroll
    for (int i = 0; i < 4; i++) {
        int gm = bm + r0 + i;
        if (gm >= M) continue;
#pragma unroll
        for (int j = 0; j < 4; j++) {
            int gn = bn + c0 + j;
            if (gn >= N) continue;
            float v = acc[i][j];
            if (EPI == 1) {
                v += bias[gn];
                v = (v > 20.f) ? v : log1pf(expf(v));
            }
            C[(size_t)gm * ldc + gn] = v;
        }
    }
}

// ---------------- depthwise causal conv (K=4) + SiLU ----------------
__global__ void conv_silu_kernel(const float* __restrict__ xz,
                                 const float* __restrict__ w,
                                 const float* __restrict__ bias,
                                 float* __restrict__ xc)
{
    int idx = blockIdx.x * blockDim.x + threadIdx.x;
    if (idx >= Mrows * DIm) return;
    int row = idx / DIm;          // b*L + l
    int c   = idx - row * DIm;
    int l   = row & (Ll - 1);
    float s = bias[c];
#pragma unroll
    for (int k = 0; k < 4; k++) {
        int ll = l - 3 + k;
        if (ll >= 0) s += w[c * 4 + k] * xz[(size_t)(row - 3 + k) * (2 * DIm) + c];
    }
    xc[idx] = s / (1.f + expf(-s));   // silu
}

// ---------------- selective scan + skip + SiLU gate (4 lanes / channel) ------
// thread group of 4 lanes per channel d; each lane owns 4 of the 16 states.
__global__ void scan_kernel4(const float* __restrict__ xc,
                             const float* __restrict__ dt,
                             const float* __restrict__ dbl,
                             const float* __restrict__ A_log,
                             const float* __restrict__ Dp,
                             const float* __restrict__ xz,
                             float* __restrict__ y)
{
    int gt = blockIdx.x * blockDim.x + threadIdx.x;   // DIm*4 threads per batch
    int d = gt >> 2;
    int q = gt & 3;
    int b = blockIdx.y;
    if (d >= DIm) return;

    float Ac[4], st[4] = {0.f, 0.f, 0.f, 0.f};
#pragma unroll
    for (int n = 0; n < 4; n++)
        Ac[n] = -expf(A_log[(size_t)d * 16 + q * 4 + n]);
    float dp = Dp[d];

    const float* xcb = xc  + (size_t)b * Ll * DIm + d;
    const float* dtb = dt  + (size_t)b * Ll * DIm + d;
    const float* zb  = xz  + (size_t)b * Ll * (2 * DIm) + DIm + d;
    const float* blb = dbl + (size_t)b * Ll * 80 + 48 + q * 4;
    float*       yb  = y   + (size_t)b * Ll * DIm + d;

    for (int l = 0; l < Ll; l++) {
        float u   = xcb[(size_t)l * DIm];
        float dtt = dtb[(size_t)l * DIm];
        float du  = dtt * u;
        const float* bl = blb + (size_t)l * 80;
        float yv = 0.f;
#pragma unroll
        for (int n = 0; n < 4; n++) {
            float e = __expf(dtt * Ac[n]);
            st[n] = fmaf(e, st[n], du * bl[n]);
            yv = fmaf(st[n], bl[16 + n], yv);
        }
        yv += __shfl_xor_sync(0xffffffffu, yv, 1);
        yv += __shfl_xor_sync(0xffffffffu, yv, 2);
        if (q == 0) {
            float z = zb[(size_t)l * (2 * DIm)];
            yv = fmaf(u, dp, yv);
            yb[(size_t)l * DIm] = yv * (z / (1.f + __expf(-z)));
        }
    }
}

// ---------------- host launcher ----------------
extern "C" void kernel_launch(void* const* d_in, const int* in_sizes, int n_in,
                              void* d_out, int out_size)
{
    const int*   ids       = (const int*)  d_in[0];
    const float* emb       = (const float*)d_in[1];
    const float* in_proj_w = (const float*)d_in[2];   // [NL, 2*DI, D]
    const float* conv_w    = (const float*)d_in[3];   // [NL, DI, 4]
    const float* conv_b    = (const float*)d_in[4];   // [NL, DI]
    const float* x_proj_w  = (const float*)d_in[5];   // [NL, 80, DI]
    const float* dt_proj_w = (const float*)d_in[6];   // [NL, DI, 48]
    const float* dt_proj_b = (const float*)d_in[7];   // [NL, DI]
    const float* A_log     = (const float*)d_in[8];   // [NL, DI, 16]
    const float* D_param   = (const float*)d_in[9];   // [NL, DI]
    const float* out_proj_w= (const float*)d_in[10];  // [NL, D, DI]
    const float* norm_w    = (const float*)d_in[11];  // [NL, D]
    const float* norm_f_w  = (const float*)d_in[12];  // [D]
    float* out = (float*)d_out;

    float* s = nullptr;
    cudaGetSymbolAddress((void**)&s, g_scratch);
    float* res = s + OFF_RES;
    float* h   = s + OFF_H;
    float* x   = s + OFF_X;
    float* xz  = s + OFF_XZ;
    float* xc  = s + OFF_XC;
    float* dt  = s + OFF_DT;
    float* y   = s + OFF_Y;
    float* dbl = s + OFF_DBL;

    embed_kernel<<<(Mrows * Dm + 255) / 256, 256>>>(ids, emb, res);

    for (int i = 0; i < NLs; i++) {
        // h = rms(res += x)
        rms_resid_kernel<<<Mrows, 256>>>(res, x, norm_w + (size_t)i * Dm, h, i > 0);

        // xz = h @ in_proj^T   [2048, 3072], K=768
        {
            dim3 g(2 * DIm / 128, Mrows / 128);
            sgemm_tn<128, 0><<<g, 256>>>(h, Dm, in_proj_w + (size_t)i * 2 * DIm * Dm,
                                         xz, 2 * DIm, Dm, nullptr);
        }

        // xc = silu(causal depthwise conv(xi) + b)
        conv_silu_kernel<<<(Mrows * DIm + 255) / 256, 256>>>(
            xz, conv_w + (size_t)i * DIm * 4, conv_b + (size_t)i * DIm, xc);

        // dbl = xc @ x_proj^T   [2048, 80], K=1536  (N=80 -> small-tile kernel)
        {
            dim3 g((80 + 63) / 64, Mrows / 64);
            gemm_atb<0><<<g, 256>>>(xc, DIm, x_proj_w + (size_t)i * 80 * DIm,
                                    dbl, 80, Mrows, 80, DIm, nullptr);
        }

        // dt = softplus(dbl[:, :48] @ dt_proj^T + dt_bias)   [2048, 1536], K=48
        {
            dim3 g(DIm / 128, Mrows / 128);
            sgemm_tn<128, 1><<<g, 256>>>(dbl, 80, dt_proj_w + (size_t)i * DIm * Rr,
                                         dt, DIm, Rr, dt_proj_b + (size_t)i * DIm);
        }

        // selective scan + D skip + silu(z) gate
        {
            dim3 g(DIm * 4 / 128, Bb);
            scan_kernel4<<<g, 128>>>(xc, dt, dbl,
                                     A_log + (size_t)i * DIm * Nst,
                                     D_param + (size_t)i * DIm, xz, y);
        }

        // x = y @ out_proj^T   [2048, 768], K=1536  (BN=64 to fill the chip)
        {
            dim3 g(Dm / 64, Mrows / 128);
            sgemm_tn<64, 0><<<g, 256>>>(y, DIm, out_proj_w + (size_t)i * Dm * DIm,
                                        x, Dm, DIm, nullptr);
        }
    }

    // final: out = rms(res + x) * norm_f_w
    rms_resid_kernel<<<Mrows, 256>>>(res, x, norm_f_w, out, 1);
}

// round 4
// speedup vs baseline: 1.9561x; 1.9561x over previous
#include <cuda_runtime.h>
#include <math.h>
#include <mma.h>

using namespace nvcuda;

typedef unsigned long long u64;

// ---------------- model constants ----------------
constexpr int Dm  = 768;
constexpr int DIm = 1536;
constexpr int Nst = 16;
constexpr int Rr  = 48;
constexpr int NLs = 8;
constexpr int Bb  = 2;
constexpr int Ll  = 1024;
constexpr int Mrows = Bb * Ll;          // 2048
constexpr float EPSf = 1e-5f;

// ---------------- scratch (static device memory; no allocations) ----------------
constexpr size_t OFF_RES = 0;
constexpr size_t OFF_H   = OFF_RES + (size_t)Mrows * Dm;
constexpr size_t OFF_X   = OFF_H   + (size_t)Mrows * Dm;
constexpr size_t OFF_XZ  = OFF_X   + (size_t)Mrows * Dm;
constexpr size_t OFF_XC  = OFF_XZ  + (size_t)Mrows * 2 * DIm;
constexpr size_t OFF_DT  = OFF_XC  + (size_t)Mrows * DIm;
constexpr size_t OFF_Y   = OFF_DT  + (size_t)Mrows * DIm;
constexpr size_t OFF_DBL = OFF_Y   + (size_t)Mrows * DIm;
constexpr size_t SCRATCH_TOTAL = OFF_DBL + (size_t)Mrows * 80;

__device__ float g_scratch[SCRATCH_TOTAL];

// ---------------- embedding gather ----------------
__global__ void embed_kernel(const int* __restrict__ ids,
                             const float* __restrict__ emb,
                             float* __restrict__ res)
{
    int idx = blockIdx.x * blockDim.x + threadIdx.x;
    if (idx >= Mrows * Dm) return;
    int row = idx / Dm;
    int c   = idx - row * Dm;
    res[idx] = emb[(size_t)ids[row] * Dm + c];
}

// ---------------- residual add + RMSNorm ----------------
__global__ void rms_resid_kernel(float* __restrict__ res,
                                 const float* __restrict__ xadd,
                                 const float* __restrict__ w,
                                 float* __restrict__ out,
                                 int addx)
{
    const int row = blockIdx.x;
    const int tid = threadIdx.x;          // 256 threads, D=768 -> 3 elems each
    float v[3];
    float local = 0.f;
#pragma unroll
    for (int j = 0; j < 3; j++) {
        int c = tid + j * 256;
        float t = res[(size_t)row * Dm + c];
        if (addx) {
            t += xadd[(size_t)row * Dm + c];
            res[(size_t)row * Dm + c] = t;
        }
        v[j] = t;
        local += t * t;
    }
#pragma unroll
    for (int o = 16; o > 0; o >>= 1) local += __shfl_xor_sync(0xffffffffu, local, o);
    __shared__ float warpsum[8];
    __shared__ float sscale;
    if ((tid & 31) == 0) warpsum[tid >> 5] = local;
    __syncthreads();
    if (tid == 0) {
        float t = 0.f;
#pragma unroll
        for (int j = 0; j < 8; j++) t += warpsum[j];
        sscale = rsqrtf(t / (float)Dm + EPSf);
    }
    __syncthreads();
    float sc = sscale;
#pragma unroll
    for (int j = 0; j < 3; j++) {
        int c = tid + j * 256;
        out[(size_t)row * Dm + c] = v[j] * sc * w[c];
    }
}

// ============================================================================
// TF32 tensor-core GEMM:  C[M,N] = A[M,K](lda) @ W[N,K]^T
// Block tile BM=128 x BN (128 or 64), BK=32.  256 threads = 8 warps (2m x 4n).
// Warp tile 64 x (BN/4).  wmma m16n16k8, fp32 accumulate.
// Requires: M%128==0, N%BN==0, K%32==0, lda%4==0, K%4==0 pointers 16B-aligned.
// ============================================================================
template <int BN>
__global__ __launch_bounds__(256)
void wmma_tn(const float* __restrict__ A, int lda,
             const float* __restrict__ W,
             float* __restrict__ C, int ldc, int K)
{
    constexpr int BM = 128;
    constexpr int BK = 32;
    constexpr int WM = 64;          // warp tile M (2 warps in m)
    constexpr int WN = BN / 4;      // warp tile N (4 warps in n): 32 or 16
    constexpr int AF = WM / 16;     // 4 a-fragments
    constexpr int BF = WN / 16;     // 2 or 1 b-fragments
    constexpr int LDS_PAD = 4;

    __shared__ float As[BM][BK + LDS_PAD];
    __shared__ float Ws[BN][BK + LDS_PAD];

    const int t    = threadIdx.x;
    const int warp = t >> 5;
    const int wm   = (warp & 1) * WM;
    const int wn   = (warp >> 1) * WN;
    const int bm   = blockIdx.y * BM;
    const int bn   = blockIdx.x * BN;

    wmma::fragment<wmma::accumulator, 16, 16, 8, float> acc[AF][BF];
#pragma unroll
    for (int i = 0; i < AF; i++)
#pragma unroll
        for (int j = 0; j < BF; j++)
            wmma::fill_fragment(acc[i][j], 0.f);

    for (int k0 = 0; k0 < K; k0 += BK) {
        // ---- stage A tile: BM x BK, float4 per thread ----
#pragma unroll
        for (int i = 0; i < (BM * BK / 4) / 256; i++) {
            int idx = t + i * 256;
            int r = idx >> 3, c4 = (idx & 7) * 4;
            float4 v = *(const float4*)(A + (size_t)(bm + r) * lda + k0 + c4);
            v.x = wmma::__float_to_tf32(v.x);
            v.y = wmma::__float_to_tf32(v.y);
            v.z = wmma::__float_to_tf32(v.z);
            v.w = wmma::__float_to_tf32(v.w);
            *(float4*)&As[r][c4] = v;
        }
        // ---- stage W tile: BN x BK ----
#pragma unroll
        for (int i = 0; i < (BN * BK / 4) / 256; i++) {
            int idx = t + i * 256;
            int r = idx >> 3, c4 = (idx & 7) * 4;
            float4 v = *(const float4*)(W + (size_t)(bn + r) * K + k0 + c4);
            v.x = wmma::__float_to_tf32(v.x);
            v.y = wmma::__float_to_tf32(v.y);
            v.z = wmma::__float_to_tf32(v.z);
            v.w = wmma::__float_to_tf32(v.w);
            *(float4*)&Ws[r][c4] = v;
        }
        __syncthreads();

#pragma unroll
        for (int kk = 0; kk < BK; kk += 8) {
            wmma::fragment<wmma::matrix_a, 16, 16, 8, wmma::precision::tf32, wmma::row_major> af[AF];
            wmma::fragment<wmma::matrix_b, 16, 16, 8, wmma::precision::tf32, wmma::col_major> bf[BF];
#pragma unroll
            for (int i = 0; i < AF; i++)
                wmma::load_matrix_sync(af[i], &As[wm + i * 16][kk], BK + LDS_PAD);
#pragma unroll
            for (int j = 0; j < BF; j++)
                wmma::load_matrix_sync(bf[j], &Ws[wn + j * 16][kk], BK + LDS_PAD);
#pragma unroll
            for (int i = 0; i < AF; i++)
#pragma unroll
                for (int j = 0; j < BF; j++)
                    wmma::mma_sync(acc[i][j], af[i], bf[j], acc[i][j]);
        }
        __syncthreads();
    }

#pragma unroll
    for (int i = 0; i < AF; i++)
#pragma unroll
        for (int j = 0; j < BF; j++)
            wmma::store_matrix_sync(&C[(size_t)(bm + wm + i * 16) * ldc + bn + wn + j * 16],
                                    acc[i][j], ldc, wmma::mem_row_major);
}

// ---------------- fp32 small GEMM (64x64 tile): x_proj, dt_proj ----------------
// EPI 0: plain   EPI 1: softplus(acc + bias[n])
template <int EPI>
__global__ void gemm_atb(const float* __restrict__ A, int lda,
                         const float* __restrict__ W,
                         float* __restrict__ C, int ldc,
                         int M, int N, int K,
                         const float* __restrict__ bias)
{
    __shared__ float As[16][68];
    __shared__ float Ws[16][68];
    const int bm = blockIdx.y * 64;
    const int bn = blockIdx.x * 64;
    const int tid = threadIdx.x;
    const int r0 = (tid >> 4) << 2;
    const int c0 = (tid & 15) << 2;
    float acc[4][4] = {};

    for (int k0 = 0; k0 < K; k0 += 16) {
#pragma unroll
        for (int i = 0; i < 4; i++) {
            int idx = tid + i * 256;
            int m = idx >> 4, k = idx & 15;
            int gm = bm + m;
            As[k][m] = (gm < M) ? A[(size_t)gm * lda + k0 + k] : 0.f;
            int gn = bn + m;
            Ws[k][m] = (gn < N) ? W[(size_t)gn * K + k0 + k] : 0.f;
        }
        __syncthreads();
#pragma unroll
        for (int k = 0; k < 16; k++) {
            float a0 = As[k][r0 + 0], a1 = As[k][r0 + 1], a2 = As[k][r0 + 2], a3 = As[k][r0 + 3];
            float b0 = Ws[k][c0 + 0], b1 = Ws[k][c0 + 1], b2 = Ws[k][c0 + 2], b3 = Ws[k][c0 + 3];
            acc[0][0] += a0 * b0; acc[0][1] += a0 * b1; acc[0][2] += a0 * b2; acc[0][3] += a0 * b3;
            acc[1][0] += a1 * b0; acc[1][1] += a1 * b1; acc[1][2] += a1 * b2; acc[1][3] += a1 * b3;
            acc[2][0] += a2 * b0; acc[2][1] += a2 * b1; acc[2][2] += a2 * b2; acc[2][3] += a2 * b3;
            acc[3][0] += a3 * b0; acc[3][1] += a3 * b1; acc[3][2] += a3 * b2; acc[3][3] += a3 * b3;
        }
        __syncthreads();
    }

#pragma unroll
    for (int i = 0; i < 4; i++) {
        int gm = bm + r0 + i;
        if (gm >= M) continue;
#pragma unroll
        for (int j = 0; j < 4; j++) {
            int gn = bn + c0 + j;
            if (gn >= N) continue;
            float v = acc[i][j];
            if (EPI == 1) {
                v += bias[gn];
                v = (v > 20.f) ? v : log1pf(expf(v));
            }
            C[(size_t)gm * ldc + gn] = v;
        }
    }
}

// ---------------- depthwise causal conv (K=4) + SiLU ----------------
__global__ void conv_silu_kernel(const float* __restrict__ xz,
                                 const float* __restrict__ w,
                                 const float* __restrict__ bias,
                                 float* __restrict__ xc)
{
    int idx = blockIdx.x * blockDim.x + threadIdx.x;
    if (idx >= Mrows * DIm) return;
    int row = idx / DIm;          // b*L + l
    int c   = idx - row * DIm;
    int l   = row & (Ll - 1);
    float s = bias[c];
#pragma unroll
    for (int k = 0; k < 4; k++) {
        int ll = l - 3 + k;
        if (ll >= 0) s += w[c * 4 + k] * xz[(size_t)(row - 3 + k) * (2 * DIm) + c];
    }
    xc[idx] = s / (1.f + expf(-s));   // silu
}

// ---------------- selective scan + skip + SiLU gate (4 lanes / channel) ------
__global__ void scan_kernel4(const float* __restrict__ xc,
                             const float* __restrict__ dt,
                             const float* __restrict__ dbl,
                             const float* __restrict__ A_log,
                             const float* __restrict__ Dp,
                             const float* __restrict__ xz,
                             float* __restrict__ y)
{
    int gt = blockIdx.x * blockDim.x + threadIdx.x;   // DIm*4 threads per batch
    int d = gt >> 2;
    int q = gt & 3;
    int b = blockIdx.y;
    if (d >= DIm) return;

    float Ac[4], st[4] = {0.f, 0.f, 0.f, 0.f};
#pragma unroll
    for (int n = 0; n < 4; n++)
        Ac[n] = -expf(A_log[(size_t)d * 16 + q * 4 + n]);
    float dp = Dp[d];

    const float* xcb = xc  + (size_t)b * Ll * DIm + d;
    const float* dtb = dt  + (size_t)b * Ll * DIm + d;
    const float* zb  = xz  + (size_t)b * Ll * (2 * DIm) + DIm + d;
    const float* blb = dbl + (size_t)b * Ll * 80 + 48 + q * 4;
    float*       yb  = y   + (size_t)b * Ll * DIm + d;

    for (int l = 0; l < Ll; l++) {
        float u   = xcb[(size_t)l * DIm];
        float dtt = dtb[(size_t)l * DIm];
        float du  = dtt * u;
        const float* bl = blb + (size_t)l * 80;
        float yv = 0.f;
#pragma unroll
        for (int n = 0; n < 4; n++) {
            float e = __expf(dtt * Ac[n]);
            st[n] = fmaf(e, st[n], du * bl[n]);
            yv = fmaf(st[n], bl[16 + n], yv);
        }
        yv += __shfl_xor_sync(0xffffffffu, yv, 1);
        yv += __shfl_xor_sync(0xffffffffu, yv, 2);
        if (q == 0) {
            float z = zb[(size_t)l * (2 * DIm)];
            yv = fmaf(u, dp, yv);
            yb[(size_t)l * DIm] = yv * (z / (1.f + __expf(-z)));
        }
    }
}

// ---------------- host launcher ----------------
extern "C" void kernel_launch(void* const* d_in, const int* in_sizes, int n_in,
                              void* d_out, int out_size)
{
    const int*   ids       = (const int*)  d_in[0];
    const float* emb       = (const float*)d_in[1];
    const float* in_proj_w = (const float*)d_in[2];   // [NL, 2*DI, D]
    const float* conv_w    = (const float*)d_in[3];   // [NL, DI, 4]
    const float* conv_b    = (const float*)d_in[4];   // [NL, DI]
    const float* x_proj_w  = (const float*)d_in[5];   // [NL, 80, DI]
    const float* dt_proj_w = (const float*)d_in[6];   // [NL, DI, 48]
    const float* dt_proj_b = (const float*)d_in[7];   // [NL, DI]
    const float* A_log     = (const float*)d_in[8];   // [NL, DI, 16]
    const float* D_param   = (const float*)d_in[9];   // [NL, DI]
    const float* out_proj_w= (const float*)d_in[10];  // [NL, D, DI]
    const float* norm_w    = (const float*)d_in[11];  // [NL, D]
    const float* norm_f_w  = (const float*)d_in[12];  // [D]
    float* out = (float*)d_out;

    float* s = nullptr;
    cudaGetSymbolAddress((void**)&s, g_scratch);
    float* res = s + OFF_RES;
    float* h   = s + OFF_H;
    float* x   = s + OFF_X;
    float* xz  = s + OFF_XZ;
    float* xc  = s + OFF_XC;
    float* dt  = s + OFF_DT;
    float* y   = s + OFF_Y;
    float* dbl = s + OFF_DBL;

    embed_kernel<<<(Mrows * Dm + 255) / 256, 256>>>(ids, emb, res);

    for (int i = 0; i < NLs; i++) {
        // h = rms(res += x)
        rms_resid_kernel<<<Mrows, 256>>>(res, x, norm_w + (size_t)i * Dm, h, i > 0);

        // xz = h @ in_proj^T   [2048, 3072], K=768  (tf32 tensor cores)
        {
            dim3 g(2 * DIm / 128, Mrows / 128);      // 24 x 16 = 384 blocks
            wmma_tn<128><<<g, 256>>>(h, Dm, in_proj_w + (size_t)i * 2 * DIm * Dm,
                                     xz, 2 * DIm, Dm);
        }

        // xc = silu(causal depthwise conv(xi) + b)
        conv_silu_kernel<<<(Mrows * DIm + 255) / 256, 256>>>(
            xz, conv_w + (size_t)i * DIm * 4, conv_b + (size_t)i * DIm, xc);

        // dbl = xc @ x_proj^T   [2048, 80], K=1536   (fp32 exact)
        {
            dim3 g((80 + 63) / 64, Mrows / 64);
            gemm_atb<0><<<g, 256>>>(xc, DIm, x_proj_w + (size_t)i * 80 * DIm,
                                    dbl, 80, Mrows, 80, DIm, nullptr);
        }

        // dt = softplus(dbl[:, :48] @ dt_proj^T + bias)  [2048, 1536], K=48  (fp32)
        {
            dim3 g(DIm / 64, Mrows / 64);
            gemm_atb<1><<<g, 256>>>(dbl, 80, dt_proj_w + (size_t)i * DIm * Rr,
                                    dt, DIm, Mrows, DIm, Rr,
                                    dt_proj_b + (size_t)i * DIm);
        }

        // selective scan + D skip + silu(z) gate
        {
            dim3 g(DIm * 4 / 128, Bb);
            scan_kernel4<<<g, 128>>>(xc, dt, dbl,
                                     A_log + (size_t)i * DIm * Nst,
                                     D_param + (size_t)i * DIm, xz, y);
        }

        // x = y @ out_proj^T   [2048, 768], K=1536  (tf32, BN=64 -> 192 blocks)
        {
            dim3 g(Dm / 64, Mrows / 128);
            wmma_tn<64><<<g, 256>>>(y, DIm, out_proj_w + (size_t)i * Dm * DIm,
                                    x, Dm, DIm);
        }
    }

    // final: out = rms(res + x) * norm_f_w
    rms_resid_kernel<<<Mrows, 256>>>(res, x, norm_f_w, out, 1);
}

// round 5
// speedup vs baseline: 3.9205x; 2.0042x over previous
#include <cuda_runtime.h>
#include <math.h>
#include <mma.h>

using namespace nvcuda;

// ---------------- model constants ----------------
constexpr int Dm  = 768;
constexpr int DIm = 1536;
constexpr int Nst = 16;
constexpr int Rr  = 48;
constexpr int NLs = 8;
constexpr int Bb  = 2;
constexpr int Ll  = 1024;
constexpr int Mrows = Bb * Ll;          // 2048
constexpr float EPSf = 1e-5f;
constexpr int CH = 8;                   // scan chunks
constexpr int CL = Ll / CH;             // 128 steps per chunk

// ---------------- scratch (static device memory; no allocations) ----------------
constexpr size_t OFF_RES = 0;
constexpr size_t OFF_H   = OFF_RES + (size_t)Mrows * Dm;
constexpr size_t OFF_X   = OFF_H   + (size_t)Mrows * Dm;
constexpr size_t OFF_XZ  = OFF_X   + (size_t)Mrows * Dm;
constexpr size_t OFF_XC  = OFF_XZ  + (size_t)Mrows * 2 * DIm;
constexpr size_t OFF_DT  = OFF_XC  + (size_t)Mrows * DIm;
constexpr size_t OFF_Y   = OFF_DT  + (size_t)Mrows * DIm;
constexpr size_t OFF_DBL = OFF_Y   + (size_t)Mrows * DIm;
constexpr size_t CHSZ    = (size_t)Bb * CH * DIm * Nst;     // per chunk-state array
constexpr size_t OFF_CHE = OFF_DBL + (size_t)Mrows * 80;
constexpr size_t OFF_APR = OFF_CHE + CHSZ;
constexpr size_t OFF_PRE = OFF_APR + CHSZ;
constexpr size_t SCRATCH_TOTAL = OFF_PRE + CHSZ;

__device__ float g_scratch[SCRATCH_TOTAL];

// ---------------- cp.async helpers ----------------
__device__ __forceinline__ void cp16(void* smem_ptr, const void* gmem_ptr)
{
    unsigned s = (unsigned)__cvta_generic_to_shared(smem_ptr);
    asm volatile("cp.async.cg.shared.global [%0], [%1], 16;\n" :: "r"(s), "l"(gmem_ptr));
}
__device__ __forceinline__ void cp_commit()
{
    asm volatile("cp.async.commit_group;\n" ::: "memory");
}
template <int N>
__device__ __forceinline__ void cp_wait()
{
    asm volatile("cp.async.wait_group %0;\n" :: "n"(N) : "memory");
}

// ---------------- embedding gather ----------------
__global__ void embed_kernel(const int* __restrict__ ids,
                             const float* __restrict__ emb,
                             float* __restrict__ res)
{
    int idx = blockIdx.x * blockDim.x + threadIdx.x;
    if (idx >= Mrows * Dm) return;
    int row = idx / Dm;
    int c   = idx - row * Dm;
    res[idx] = emb[(size_t)ids[row] * Dm + c];
}

// ---------------- residual add + RMSNorm ----------------
__global__ void rms_resid_kernel(float* __restrict__ res,
                                 const float* __restrict__ xadd,
                                 const float* __restrict__ w,
                                 float* __restrict__ out,
                                 int addx)
{
    const int row = blockIdx.x;
    const int tid = threadIdx.x;          // 256 threads, D=768 -> 3 elems each
    float v[3];
    float local = 0.f;
#pragma unroll
    for (int j = 0; j < 3; j++) {
        int c = tid + j * 256;
        float t = res[(size_t)row * Dm + c];
        if (addx) {
            t += xadd[(size_t)row * Dm + c];
            res[(size_t)row * Dm + c] = t;
        }
        v[j] = t;
        local += t * t;
    }
#pragma unroll
    for (int o = 16; o > 0; o >>= 1) local += __shfl_xor_sync(0xffffffffu, local, o);
    __shared__ float warpsum[8];
    __shared__ float sscale;
    if ((tid & 31) == 0) warpsum[tid >> 5] = local;
    __syncthreads();
    if (tid == 0) {
        float t = 0.f;
#pragma unroll
        for (int j = 0; j < 8; j++) t += warpsum[j];
        sscale = rsqrtf(t / (float)Dm + EPSf);
    }
    __syncthreads();
    float sc = sscale;
#pragma unroll
    for (int j = 0; j < 3; j++) {
        int c = tid + j * 256;
        out[(size_t)row * Dm + c] = v[j] * sc * w[c];
    }
}

// ============================================================================
// TF32 tensor-core GEMM, cp.async double-buffered.
// C[M,N] = A[M,K](lda) @ W[N,K]^T.  BM=128, BN in {128,64}, BK=32.
// 256 threads = 8 warps (2m x 4n), warp tile 64 x BN/4, wmma m16n16k8.
// Dynamic smem: As[2][128][36] + Ws[2][BN][36].
// Requires: M%128==0, N%BN==0, K%32==0, all row strides multiple of 4 floats.
// ============================================================================
template <int BN>
__global__ __launch_bounds__(256)
void wmma_tn(const float* __restrict__ A, int lda,
             const float* __restrict__ W,
             float* __restrict__ C, int ldc, int K)
{
    constexpr int BM = 128;
    constexpr int BK = 32;
    constexpr int LD = BK + 4;     // 36 floats, 144B rows (16B aligned)
    constexpr int WM = 64;
    constexpr int WN = BN / 4;
    constexpr int AF = WM / 16;
    constexpr int BF = WN / 16;

    extern __shared__ float smemf[];
    float* AsB = smemf;                       // 2 * BM * LD
    float* WsB = smemf + 2 * BM * LD;         // 2 * BN * LD

    const int t    = threadIdx.x;
    const int warp = t >> 5;
    const int wm   = (warp & 1) * WM;
    const int wn   = (warp >> 1) * WN;
    const int bm   = blockIdx.y * BM;
    const int bn   = blockIdx.x * BN;

    // loader mapping: chunk index -> (row, 4-float col)
    // A tile: BM*8 chunks, W tile: BN*8 chunks
    auto issue = [&](int stage, int k0) {
#pragma unroll
        for (int i = 0; i < (BM * 8) / 256; i++) {
            int idx = t + i * 256;
            int r = idx >> 3, c4 = (idx & 7) * 4;
            cp16(&AsB[((size_t)stage * BM + r) * LD + c4],
                 A + (size_t)(bm + r) * lda + k0 + c4);
        }
#pragma unroll
        for (int i = 0; i < (BN * 8) / 256; i++) {
            int idx = t + i * 256;
            int r = idx >> 3, c4 = (idx & 7) * 4;
            cp16(&WsB[((size_t)stage * BN + r) * LD + c4],
                 W + (size_t)(bn + r) * K + k0 + c4);
        }
        cp_commit();
    };

    wmma::fragment<wmma::accumulator, 16, 16, 8, float> acc[AF][BF];
#pragma unroll
    for (int i = 0; i < AF; i++)
#pragma unroll
        for (int j = 0; j < BF; j++)
            wmma::fill_fragment(acc[i][j], 0.f);

    const int nt = K / BK;
    issue(0, 0);

    for (int tt = 0; tt < nt; ++tt) {
        const int buf = tt & 1;
        if (tt + 1 < nt) {
            issue(buf ^ 1, (tt + 1) * BK);
            cp_wait<1>();
        } else {
            cp_wait<0>();
        }
        __syncthreads();

        const float* Abuf = AsB + (size_t)buf * BM * LD;
        const float* Wbuf = WsB + (size_t)buf * BN * LD;
#pragma unroll
        for (int kk = 0; kk < BK; kk += 8) {
            wmma::fragment<wmma::matrix_a, 16, 16, 8, wmma::precision::tf32, wmma::row_major> af[AF];
            wmma::fragment<wmma::matrix_b, 16, 16, 8, wmma::precision::tf32, wmma::col_major> bf[BF];
#pragma unroll
            for (int i = 0; i < AF; i++)
                wmma::load_matrix_sync(af[i], Abuf + (size_t)(wm + i * 16) * LD + kk, LD);
#pragma unroll
            for (int j = 0; j < BF; j++)
                wmma::load_matrix_sync(bf[j], Wbuf + (size_t)(wn + j * 16) * LD + kk, LD);
#pragma unroll
            for (int i = 0; i < AF; i++)
#pragma unroll
                for (int j = 0; j < BF; j++)
                    wmma::mma_sync(acc[i][j], af[i], bf[j], acc[i][j]);
        }
        __syncthreads();
    }

#pragma unroll
    for (int i = 0; i < AF; i++)
#pragma unroll
        for (int j = 0; j < BF; j++)
            wmma::store_matrix_sync(&C[(size_t)(bm + wm + i * 16) * ldc + bn + wn + j * 16],
                                    acc[i][j], ldc, wmma::mem_row_major);
}

// ---------------- fp32 small GEMM (64x64 tile): x_proj, dt_proj ----------------
template <int EPI>
__global__ void gemm_atb(const float* __restrict__ A, int lda,
                         const float* __restrict__ W,
                         float* __restrict__ C, int ldc,
                         int M, int N, int K,
                         const float* __restrict__ bias)
{
    __shared__ float As[16][68];
    __shared__ float Ws[16][68];
    const int bm = blockIdx.y * 64;
    const int bn = blockIdx.x * 64;
    const int tid = threadIdx.x;
    const int r0 = (tid >> 4) << 2;
    const int c0 = (tid & 15) << 2;
    float acc[4][4] = {};

    for (int k0 = 0; k0 < K; k0 += 16) {
#pragma unroll
        for (int i = 0; i < 4; i++) {
            int idx = tid + i * 256;
            int m = idx >> 4, k = idx & 15;
            int gm = bm + m;
            As[k][m] = (gm < M) ? A[(size_t)gm * lda + k0 + k] : 0.f;
            int gn = bn + m;
            Ws[k][m] = (gn < N) ? W[(size_t)gn * K + k0 + k] : 0.f;
        }
        __syncthreads();
#pragma unroll
        for (int k = 0; k < 16; k++) {
            float a0 = As[k][r0 + 0], a1 = As[k][r0 + 1], a2 = As[k][r0 + 2], a3 = As[k][r0 + 3];
            float b0 = Ws[k][c0 + 0], b1 = Ws[k][c0 + 1], b2 = Ws[k][c0 + 2], b3 = Ws[k][c0 + 3];
            acc[0][0] += a0 * b0; acc[0][1] += a0 * b1; acc[0][2] += a0 * b2; acc[0][3] += a0 * b3;
            acc[1][0] += a1 * b0; acc[1][1] += a1 * b1; acc[1][2] += a1 * b2; acc[1][3] += a1 * b3;
            acc[2][0] += a2 * b0; acc[2][1] += a2 * b1; acc[2][2] += a2 * b2; acc[2][3] += a2 * b3;
            acc[3][0] += a3 * b0; acc[3][1] += a3 * b1; acc[3][2] += a3 * b2; acc[3][3] += a3 * b3;
        }
        __syncthreads();
    }

#pragma unroll
    for (int i = 0; i < 4; i++) {
        int gm = bm + r0 + i;
        if (gm >= M) continue;
#pragma unroll
        for (int j = 0; j < 4; j++) {
            int gn = bn + c0 + j;
            if (gn >= N) continue;
            float v = acc[i][j];
            if (EPI == 1) {
                v += bias[gn];
                v = (v > 20.f) ? v : log1pf(expf(v));
            }
            C[(size_t)gm * ldc + gn] = v;
        }
    }
}

// ---------------- depthwise causal conv (K=4) + SiLU ----------------
__global__ void conv_silu_kernel(const float* __restrict__ xz,
                                 const float* __restrict__ w,
                                 const float* __restrict__ bias,
                                 float* __restrict__ xc)
{
    int idx = blockIdx.x * blockDim.x + threadIdx.x;
    if (idx >= Mrows * DIm) return;
    int row = idx / DIm;          // b*L + l
    int c   = idx - row * DIm;
    int l   = row & (Ll - 1);
    float s = bias[c];
#pragma unroll
    for (int k = 0; k < 4; k++) {
        int ll = l - 3 + k;
        if (ll >= 0) s += w[c * 4 + k] * xz[(size_t)(row - 3 + k) * (2 * DIm) + c];
    }
    xc[idx] = s / (1.f + expf(-s));   // silu
}

// ============================================================================
// Chunked selective scan (3 phases), 4 lanes per channel, CH chunks of CL.
// ============================================================================

// phase 1: per-chunk local scan from zero state; store end-state + decay product
__global__ void scan_pass1(const float* __restrict__ xc,
                           const float* __restrict__ dt,
                           const float* __restrict__ dbl,
                           const float* __restrict__ A_log,
                           float* __restrict__ chk_end,
                           float* __restrict__ aprod)
{
    int gt = blockIdx.x * blockDim.x + threadIdx.x;
    int d = gt >> 2;
    int q = gt & 3;
    int c = blockIdx.y;
    int b = blockIdx.z;
    if (d >= DIm) return;

    float Ac[4], st[4] = {0.f, 0.f, 0.f, 0.f}, ap[4] = {1.f, 1.f, 1.f, 1.f};
#pragma unroll
    for (int n = 0; n < 4; n++)
        Ac[n] = -expf(A_log[(size_t)d * 16 + q * 4 + n]);

    const int l0 = c * CL;
    const float* xcb = xc  + ((size_t)b * Ll + l0) * DIm + d;
    const float* dtb = dt  + ((size_t)b * Ll + l0) * DIm + d;
    const float* blb = dbl + ((size_t)b * Ll + l0) * 80 + 48 + q * 4;

    for (int l = 0; l < CL; l++) {
        float u   = xcb[(size_t)l * DIm];
        float dtt = dtb[(size_t)l * DIm];
        float du  = dtt * u;
        const float* bl = blb + (size_t)l * 80;
#pragma unroll
        for (int n = 0; n < 4; n++) {
            float e = __expf(dtt * Ac[n]);
            st[n] = fmaf(e, st[n], du * bl[n]);
            ap[n] *= e;
        }
    }
    size_t base = (((size_t)b * CH + c) * DIm + d) * 16 + q * 4;
#pragma unroll
    for (int n = 0; n < 4; n++) {
        chk_end[base + n] = st[n];
        aprod[base + n]   = ap[n];
    }
}

// phase 2: sequential composition over chunks -> initial state per chunk
__global__ void scan_pass2(const float* __restrict__ chk_end,
                           const float* __restrict__ aprod,
                           float* __restrict__ chk_pref)
{
    int idx = blockIdx.x * blockDim.x + threadIdx.x;   // b*DIm*16
    if (idx >= Bb * DIm * Nst) return;
    int b = idx / (DIm * Nst);
    int r = idx - b * (DIm * Nst);
    float hv = 0.f;
#pragma unroll
    for (int c = 0; c < CH; c++) {
        size_t o = ((size_t)b * CH + c) * DIm * Nst + r;
        chk_pref[o] = hv;
        hv = fmaf(aprod[o], hv, chk_end[o]);
    }
}

// phase 3: recompute within chunk from corrected init; emit y with gate
__global__ void scan_pass3(const float* __restrict__ xc,
                           const float* __restrict__ dt,
                           const float* __restrict__ dbl,
                           const float* __restrict__ A_log,
                           const float* __restrict__ Dp,
                           const float* __restrict__ xz,
                           const float* __restrict__ chk_pref,
                           float* __restrict__ y)
{
    int gt = blockIdx.x * blockDim.x + threadIdx.x;
    int d = gt >> 2;
    int q = gt & 3;
    int c = blockIdx.y;
    int b = blockIdx.z;
    if (d >= DIm) return;

    float Ac[4], st[4];
#pragma unroll
    for (int n = 0; n < 4; n++)
        Ac[n] = -expf(A_log[(size_t)d * 16 + q * 4 + n]);
    {
        size_t base = (((size_t)b * CH + c) * DIm + d) * 16 + q * 4;
#pragma unroll
        for (int n = 0; n < 4; n++) st[n] = chk_pref[base + n];
    }
    float dp = Dp[d];

    const int l0 = c * CL;
    const float* xcb = xc  + ((size_t)b * Ll + l0) * DIm + d;
    const float* dtb = dt  + ((size_t)b * Ll + l0) * DIm + d;
    const float* zb  = xz  + ((size_t)b * Ll + l0) * (2 * DIm) + DIm + d;
    const float* blb = dbl + ((size_t)b * Ll + l0) * 80 + 48 + q * 4;
    float*       yb  = y   + ((size_t)b * Ll + l0) * DIm + d;

    for (int l = 0; l < CL; l++) {
        float u   = xcb[(size_t)l * DIm];
        float dtt = dtb[(size_t)l * DIm];
        float du  = dtt * u;
        const float* bl = blb + (size_t)l * 80;
        float yv = 0.f;
#pragma unroll
        for (int n = 0; n < 4; n++) {
            float e = __expf(dtt * Ac[n]);
            st[n] = fmaf(e, st[n], du * bl[n]);
            yv = fmaf(st[n], bl[16 + n], yv);
        }
        yv += __shfl_xor_sync(0xffffffffu, yv, 1);
        yv += __shfl_xor_sync(0xffffffffu, yv, 2);
        if (q == 0) {
            float z = zb[(size_t)l * (2 * DIm)];
            yv = fmaf(u, dp, yv);
            yb[(size_t)l * DIm] = yv * (z / (1.f + __expf(-z)));
        }
    }
}

// ---------------- host launcher ----------------
extern "C" void kernel_launch(void* const* d_in, const int* in_sizes, int n_in,
                              void* d_out, int out_size)
{
    const int*   ids       = (const int*)  d_in[0];
    const float* emb       = (const float*)d_in[1];
    const float* in_proj_w = (const float*)d_in[2];   // [NL, 2*DI, D]
    const float* conv_w    = (const float*)d_in[3];   // [NL, DI, 4]
    const float* conv_b    = (const float*)d_in[4];   // [NL, DI]
    const float* x_proj_w  = (const float*)d_in[5];   // [NL, 80, DI]
    const float* dt_proj_w = (const float*)d_in[6];   // [NL, DI, 48]
    const float* dt_proj_b = (const float*)d_in[7];   // [NL, DI]
    const float* A_log     = (const float*)d_in[8];   // [NL, DI, 16]
    const float* D_param   = (const float*)d_in[9];   // [NL, DI]
    const float* out_proj_w= (const float*)d_in[10];  // [NL, D, DI]
    const float* norm_w    = (const float*)d_in[11];  // [NL, D]
    const float* norm_f_w  = (const float*)d_in[12];  // [D]
    float* out = (float*)d_out;

    float* s = nullptr;
    cudaGetSymbolAddress((void**)&s, g_scratch);
    float* res = s + OFF_RES;
    float* h   = s + OFF_H;
    float* x   = s + OFF_X;
    float* xz  = s + OFF_XZ;
    float* xc  = s + OFF_XC;
    float* dt  = s + OFF_DT;
    float* y   = s + OFF_Y;
    float* dbl = s + OFF_DBL;
    float* che = s + OFF_CHE;
    float* apr = s + OFF_APR;
    float* pre = s + OFF_PRE;

    constexpr int LD = 36;
    const int smem128 = (2 * 128 * LD + 2 * 128 * LD) * 4;   // 73728
    const int smem64  = (2 * 128 * LD + 2 * 64  * LD) * 4;   // 55296
    cudaFuncSetAttribute(wmma_tn<128>, cudaFuncAttributeMaxDynamicSharedMemorySize, smem128);
    cudaFuncSetAttribute(wmma_tn<64>,  cudaFuncAttributeMaxDynamicSharedMemorySize, smem64);

    embed_kernel<<<(Mrows * Dm + 255) / 256, 256>>>(ids, emb, res);

    for (int i = 0; i < NLs; i++) {
        // h = rms(res += x)
        rms_resid_kernel<<<Mrows, 256>>>(res, x, norm_w + (size_t)i * Dm, h, i > 0);

        // xz = h @ in_proj^T   [2048, 3072], K=768  (tf32 tensor cores)
        {
            dim3 g(2 * DIm / 128, Mrows / 128);      // 24 x 16 = 384 blocks
            wmma_tn<128><<<g, 256, smem128>>>(h, Dm, in_proj_w + (size_t)i * 2 * DIm * Dm,
                                              xz, 2 * DIm, Dm);
        }

        // xc = silu(causal depthwise conv(xi) + b)
        conv_silu_kernel<<<(Mrows * DIm + 255) / 256, 256>>>(
            xz, conv_w + (size_t)i * DIm * 4, conv_b + (size_t)i * DIm, xc);

        // dbl = xc @ x_proj^T   [2048, 80], K=1536   (fp32 exact)
        {
            dim3 g((80 + 63) / 64, Mrows / 64);
            gemm_atb<0><<<g, 256>>>(xc, DIm, x_proj_w + (size_t)i * 80 * DIm,
                                    dbl, 80, Mrows, 80, DIm, nullptr);
        }

        // dt = softplus(dbl[:, :48] @ dt_proj^T + bias)  [2048, 1536], K=48  (fp32)
        {
            dim3 g(DIm / 64, Mrows / 64);
            gemm_atb<1><<<g, 256>>>(dbl, 80, dt_proj_w + (size_t)i * DIm * Rr,
                                    dt, DIm, Mrows, DIm, Rr,
                                    dt_proj_b + (size_t)i * DIm);
        }

        // chunked selective scan
        {
            dim3 g1(DIm * 4 / 128, CH, Bb);
            scan_pass1<<<g1, 128>>>(xc, dt, dbl, A_log + (size_t)i * DIm * Nst, che, apr);
            scan_pass2<<<(Bb * DIm * Nst + 255) / 256, 256>>>(che, apr, pre);
            scan_pass3<<<g1, 128>>>(xc, dt, dbl, A_log + (size_t)i * DIm * Nst,
                                    D_param + (size_t)i * DIm, xz, pre, y);
        }

        // x = y @ out_proj^T   [2048, 768], K=1536  (tf32, BN=64 -> 192 blocks)
        {
            dim3 g(Dm / 64, Mrows / 128);
            wmma_tn<64><<<g, 256, smem64>>>(y, DIm, out_proj_w + (size_t)i * Dm * DIm,
                                            x, Dm, DIm);
        }
    }

    // final: out = rms(res + x) * norm_f_w
    rms_resid_kernel<<<Mrows, 256>>>(res, x, norm_f_w, out, 1);
}

// round 6
// speedup vs baseline: 4.2157x; 1.0753x over previous
#include <cuda_runtime.h>
#include <math.h>
#include <mma.h>

using namespace nvcuda;

// ---------------- model constants ----------------
constexpr int Dm  = 768;
constexpr int DIm = 1536;
constexpr int Nst = 16;
constexpr int Rr  = 48;
constexpr int NLs = 8;
constexpr int Bb  = 2;
constexpr int Ll  = 1024;
constexpr int Mrows = Bb * Ll;          // 2048
constexpr float EPSf = 1e-5f;
constexpr int CH = 16;                  // scan chunks
constexpr int CL = Ll / CH;             // 64 steps per chunk
constexpr int DBL_LD = 128;             // padded dbl row stride

// ---------------- scratch (static device memory; no allocations) ----------------
constexpr size_t OFF_RES = 0;
constexpr size_t OFF_H   = OFF_RES + (size_t)Mrows * Dm;
constexpr size_t OFF_X   = OFF_H   + (size_t)Mrows * Dm;
constexpr size_t OFF_XZ  = OFF_X   + (size_t)Mrows * Dm;
constexpr size_t OFF_XC  = OFF_XZ  + (size_t)Mrows * 2 * DIm;
constexpr size_t OFF_DT  = OFF_XC  + (size_t)Mrows * DIm;       // dt_lin (pre-bias/softplus)
constexpr size_t OFF_Y   = OFF_DT  + (size_t)Mrows * DIm;
constexpr size_t OFF_DBL = OFF_Y   + (size_t)Mrows * DIm;       // padded: Mrows x 128
constexpr size_t CHSZ    = (size_t)Bb * CH * DIm * Nst;
constexpr size_t OFF_CHE = OFF_DBL + (size_t)Mrows * DBL_LD;
constexpr size_t OFF_APR = OFF_CHE + CHSZ;
constexpr size_t OFF_PRE = OFF_APR + CHSZ;
constexpr size_t OFF_XWP = OFF_PRE + CHSZ;                      // [NL,128,DIm]
constexpr size_t OFF_DWP = OFF_XWP + (size_t)NLs * 128 * DIm;   // [NL,DIm,64]
constexpr size_t SCRATCH_TOTAL = OFF_DWP + (size_t)NLs * DIm * 64;

__device__ float g_scratch[SCRATCH_TOTAL];

// ---------------- cp.async helpers ----------------
__device__ __forceinline__ void cp16(void* smem_ptr, const void* gmem_ptr)
{
    unsigned s = (unsigned)__cvta_generic_to_shared(smem_ptr);
    asm volatile("cp.async.cg.shared.global [%0], [%1], 16;\n" :: "r"(s), "l"(gmem_ptr));
}
__device__ __forceinline__ void cp_commit()
{
    asm volatile("cp.async.commit_group;\n" ::: "memory");
}
template <int N>
__device__ __forceinline__ void cp_wait()
{
    asm volatile("cp.async.wait_group %0;\n" :: "n"(N) : "memory");
}

// ---------------- weight padding (run each launch; deterministic) ----------------
// xw_pad[l][r][k]: r<80 -> x_proj_w[l][r][k], else 0.
__global__ void pad_xw_kernel(const float* __restrict__ xw, float* __restrict__ xwp)
{
    int idx = blockIdx.x * blockDim.x + threadIdx.x;
    if (idx >= NLs * 128 * DIm) return;
    int l = idx / (128 * DIm);
    int rem = idx - l * (128 * DIm);
    int r = rem / DIm;
    int k = rem - r * DIm;
    xwp[idx] = (r < 80) ? xw[((size_t)l * 80 + r) * DIm + k] : 0.f;
}
// dw_pad[l][d][c]: c<48 -> dt_proj_w[l][d][c], else 0.
__global__ void pad_dw_kernel(const float* __restrict__ dw, float* __restrict__ dwp)
{
    int idx = blockIdx.x * blockDim.x + threadIdx.x;
    if (idx >= NLs * DIm * 64) return;
    int l = idx / (DIm * 64);
    int rem = idx - l * (DIm * 64);
    int d = rem / 64;
    int c = rem - d * 64;
    dwp[idx] = (c < 48) ? dw[((size_t)l * DIm + d) * 48 + c] : 0.f;
}

// ---------------- embedding gather ----------------
__global__ void embed_kernel(const int* __restrict__ ids,
                             const float* __restrict__ emb,
                             float* __restrict__ res)
{
    int idx = blockIdx.x * blockDim.x + threadIdx.x;
    if (idx >= Mrows * Dm) return;
    int row = idx / Dm;
    int c   = idx - row * Dm;
    res[idx] = emb[(size_t)ids[row] * Dm + c];
}

// ---------------- residual add + RMSNorm ----------------
__global__ void rms_resid_kernel(float* __restrict__ res,
                                 const float* __restrict__ xadd,
                                 const float* __restrict__ w,
                                 float* __restrict__ out,
                                 int addx)
{
    const int row = blockIdx.x;
    const int tid = threadIdx.x;
    float v[3];
    float local = 0.f;
#pragma unroll
    for (int j = 0; j < 3; j++) {
        int c = tid + j * 256;
        float t = res[(size_t)row * Dm + c];
        if (addx) {
            t += xadd[(size_t)row * Dm + c];
            res[(size_t)row * Dm + c] = t;
        }
        v[j] = t;
        local += t * t;
    }
#pragma unroll
    for (int o = 16; o > 0; o >>= 1) local += __shfl_xor_sync(0xffffffffu, local, o);
    __shared__ float warpsum[8];
    __shared__ float sscale;
    if ((tid & 31) == 0) warpsum[tid >> 5] = local;
    __syncthreads();
    if (tid == 0) {
        float t = 0.f;
#pragma unroll
        for (int j = 0; j < 8; j++) t += warpsum[j];
        sscale = rsqrtf(t / (float)Dm + EPSf);
    }
    __syncthreads();
    float sc = sscale;
#pragma unroll
    for (int j = 0; j < 3; j++) {
        int c = tid + j * 256;
        out[(size_t)row * Dm + c] = v[j] * sc * w[c];
    }
}

// ============================================================================
// TF32 tensor-core GEMM, cp.async double-buffered, RN-converted fragments.
// C[M,N] = A[M,K](lda) @ W[N,K]^T(row stride = K).  BM=128, BN in {128,64}.
// 256 threads = 8 warps (2m x 4n), warp tile 64 x BN/4, wmma m16n16k8.
// Requires: M%128==0, N%BN==0, K%32==0, rows 16B-aligned.
// ============================================================================
template <int BN>
__global__ __launch_bounds__(256)
void wmma_tn(const float* __restrict__ A, int lda,
             const float* __restrict__ W,
             float* __restrict__ C, int ldc, int K)
{
    constexpr int BM = 128;
    constexpr int BK = 32;
    constexpr int LD = BK + 4;
    constexpr int WM = 64;
    constexpr int WN = BN / 4;
    constexpr int AF = WM / 16;
    constexpr int BF = WN / 16;

    extern __shared__ float smemf[];
    float* AsB = smemf;                       // 2 * BM * LD
    float* WsB = smemf + 2 * BM * LD;         // 2 * BN * LD

    const int t    = threadIdx.x;
    const int warp = t >> 5;
    const int wm   = (warp & 1) * WM;
    const int wn   = (warp >> 1) * WN;
    const int bm   = blockIdx.y * BM;
    const int bn   = blockIdx.x * BN;

    auto issue = [&](int stage, int k0) {
#pragma unroll
        for (int i = 0; i < (BM * 8) / 256; i++) {
            int idx = t + i * 256;
            int r = idx >> 3, c4 = (idx & 7) * 4;
            cp16(&AsB[((size_t)stage * BM + r) * LD + c4],
                 A + (size_t)(bm + r) * lda + k0 + c4);
        }
#pragma unroll
        for (int i = 0; i < (BN * 8) / 256; i++) {
            int idx = t + i * 256;
            int r = idx >> 3, c4 = (idx & 7) * 4;
            cp16(&WsB[((size_t)stage * BN + r) * LD + c4],
                 W + (size_t)(bn + r) * K + k0 + c4);
        }
        cp_commit();
    };

    wmma::fragment<wmma::accumulator, 16, 16, 8, float> acc[AF][BF];
#pragma unroll
    for (int i = 0; i < AF; i++)
#pragma unroll
        for (int j = 0; j < BF; j++)
            wmma::fill_fragment(acc[i][j], 0.f);

    const int nt = K / BK;
    issue(0, 0);

    for (int tt = 0; tt < nt; ++tt) {
        const int buf = tt & 1;
        if (tt + 1 < nt) {
            issue(buf ^ 1, (tt + 1) * BK);
            cp_wait<1>();
        } else {
            cp_wait<0>();
        }
        __syncthreads();

        const float* Abuf = AsB + (size_t)buf * BM * LD;
        const float* Wbuf = WsB + (size_t)buf * BN * LD;
#pragma unroll
        for (int kk = 0; kk < BK; kk += 8) {
            wmma::fragment<wmma::matrix_a, 16, 16, 8, wmma::precision::tf32, wmma::row_major> af[AF];
            wmma::fragment<wmma::matrix_b, 16, 16, 8, wmma::precision::tf32, wmma::col_major> bf[BF];
#pragma unroll
            for (int i = 0; i < AF; i++) {
                wmma::load_matrix_sync(af[i], Abuf + (size_t)(wm + i * 16) * LD + kk, LD);
#pragma unroll
                for (int e = 0; e < af[i].num_elements; e++)
                    af[i].x[e] = wmma::__float_to_tf32(af[i].x[e]);
            }
#pragma unroll
            for (int j = 0; j < BF; j++) {
                wmma::load_matrix_sync(bf[j], Wbuf + (size_t)(wn + j * 16) * LD + kk, LD);
#pragma unroll
                for (int e = 0; e < bf[j].num_elements; e++)
                    bf[j].x[e] = wmma::__float_to_tf32(bf[j].x[e]);
            }
#pragma unroll
            for (int i = 0; i < AF; i++)
#pragma unroll
                for (int j = 0; j < BF; j++)
                    wmma::mma_sync(acc[i][j], af[i], bf[j], acc[i][j]);
        }
        __syncthreads();
    }

#pragma unroll
    for (int i = 0; i < AF; i++)
#pragma unroll
        for (int j = 0; j < BF; j++)
            wmma::store_matrix_sync(&C[(size_t)(bm + wm + i * 16) * ldc + bn + wn + j * 16],
                                    acc[i][j], ldc, wmma::mem_row_major);
}

// ---------------- depthwise causal conv (K=4) + SiLU ----------------
__global__ void conv_silu_kernel(const float* __restrict__ xz,
                                 const float* __restrict__ w,
                                 const float* __restrict__ bias,
                                 float* __restrict__ xc)
{
    int idx = blockIdx.x * blockDim.x + threadIdx.x;
    if (idx >= Mrows * DIm) return;
    int row = idx / DIm;
    int c   = idx - row * DIm;
    int l   = row & (Ll - 1);
    float s = bias[c];
#pragma unroll
    for (int k = 0; k < 4; k++) {
        int ll = l - 3 + k;
        if (ll >= 0) s += w[c * 4 + k] * xz[(size_t)(row - 3 + k) * (2 * DIm) + c];
    }
    xc[idx] = s / (1.f + expf(-s));
}

// ============================================================================
// Chunked selective scan (3 phases), 4 lanes per channel, CH chunks of CL.
// dt input is dt_lin (pre bias/softplus); softplus applied inline in fp32.
// ============================================================================
__device__ __forceinline__ float softplus_f(float x)
{
    return (x > 20.f) ? x : log1pf(__expf(x));
}

// phase 1: per-chunk local scan from zero state; store end-state + decay product
__global__ void scan_pass1(const float* __restrict__ xc,
                           const float* __restrict__ dtl,
                           const float* __restrict__ dbl,
                           const float* __restrict__ A_log,
                           const float* __restrict__ dtb_bias,
                           float* __restrict__ chk_end,
                           float* __restrict__ aprod)
{
    int gt = blockIdx.x * blockDim.x + threadIdx.x;
    int d = gt >> 2;
    int q = gt & 3;
    int c = blockIdx.y;
    int b = blockIdx.z;
    if (d >= DIm) return;

    float Ac[4], st[4] = {0.f, 0.f, 0.f, 0.f}, ap[4] = {1.f, 1.f, 1.f, 1.f};
#pragma unroll
    for (int n = 0; n < 4; n++)
        Ac[n] = -expf(A_log[(size_t)d * 16 + q * 4 + n]);
    const float db = dtb_bias[d];

    const int l0 = c * CL;
    const float* xcb = xc  + ((size_t)b * Ll + l0) * DIm + d;
    const float* dtb = dtl + ((size_t)b * Ll + l0) * DIm + d;
    const float* blb = dbl + ((size_t)b * Ll + l0) * DBL_LD + 48 + q * 4;

    for (int l = 0; l < CL; l++) {
        float u   = xcb[(size_t)l * DIm];
        float dtt = softplus_f(dtb[(size_t)l * DIm] + db);
        float du  = dtt * u;
        const float* bl = blb + (size_t)l * DBL_LD;
#pragma unroll
        for (int n = 0; n < 4; n++) {
            float e = __expf(dtt * Ac[n]);
            st[n] = fmaf(e, st[n], du * bl[n]);
            ap[n] *= e;
        }
    }
    size_t base = (((size_t)b * CH + c) * DIm + d) * 16 + q * 4;
#pragma unroll
    for (int n = 0; n < 4; n++) {
        chk_end[base + n] = st[n];
        aprod[base + n]   = ap[n];
    }
}

// phase 2: sequential composition over chunks -> initial state per chunk
__global__ void scan_pass2(const float* __restrict__ chk_end,
                           const float* __restrict__ aprod,
                           float* __restrict__ chk_pref)
{
    int idx = blockIdx.x * blockDim.x + threadIdx.x;
    if (idx >= Bb * DIm * Nst) return;
    int b = idx / (DIm * Nst);
    int r = idx - b * (DIm * Nst);
    float hv = 0.f;
#pragma unroll
    for (int c = 0; c < CH; c++) {
        size_t o = ((size_t)b * CH + c) * DIm * Nst + r;
        chk_pref[o] = hv;
        hv = fmaf(aprod[o], hv, chk_end[o]);
    }
}

// phase 3: recompute within chunk from corrected init; emit y with gate
__global__ void scan_pass3(const float* __restrict__ xc,
                           const float* __restrict__ dtl,
                           const float* __restrict__ dbl,
                           const float* __restrict__ A_log,
                           const float* __restrict__ dtb_bias,
                           const float* __restrict__ Dp,
                           const float* __restrict__ xz,
                           const float* __restrict__ chk_pref,
                           float* __restrict__ y)
{
    int gt = blockIdx.x * blockDim.x + threadIdx.x;
    int d = gt >> 2;
    int q = gt & 3;
    int c = blockIdx.y;
    int b = blockIdx.z;
    if (d >= DIm) return;

    float Ac[4], st[4];
#pragma unroll
    for (int n = 0; n < 4; n++)
        Ac[n] = -expf(A_log[(size_t)d * 16 + q * 4 + n]);
    {
        size_t base = (((size_t)b * CH + c) * DIm + d) * 16 + q * 4;
#pragma unroll
        for (int n = 0; n < 4; n++) st[n] = chk_pref[base + n];
    }
    const float db = dtb_bias[d];
    float dp = Dp[d];

    const int l0 = c * CL;
    const float* xcb = xc  + ((size_t)b * Ll + l0) * DIm + d;
    const float* dtb = dtl + ((size_t)b * Ll + l0) * DIm + d;
    const float* zb  = xz  + ((size_t)b * Ll + l0) * (2 * DIm) + DIm + d;
    const float* blb = dbl + ((size_t)b * Ll + l0) * DBL_LD + 48 + q * 4;
    float*       yb  = y   + ((size_t)b * Ll + l0) * DIm + d;

    for (int l = 0; l < CL; l++) {
        float u   = xcb[(size_t)l * DIm];
        float dtt = softplus_f(dtb[(size_t)l * DIm] + db);
        float du  = dtt * u;
        const float* bl = blb + (size_t)l * DBL_LD;
        float yv = 0.f;
#pragma unroll
        for (int n = 0; n < 4; n++) {
            float e = __expf(dtt * Ac[n]);
            st[n] = fmaf(e, st[n], du * bl[n]);
            yv = fmaf(st[n], bl[16 + n], yv);
        }
        yv += __shfl_xor_sync(0xffffffffu, yv, 1);
        yv += __shfl_xor_sync(0xffffffffu, yv, 2);
        if (q == 0) {
            float z = zb[(size_t)l * (2 * DIm)];
            yv = fmaf(u, dp, yv);
            yb[(size_t)l * DIm] = yv * (z / (1.f + __expf(-z)));
        }
    }
}

// ---------------- host launcher ----------------
extern "C" void kernel_launch(void* const* d_in, const int* in_sizes, int n_in,
                              void* d_out, int out_size)
{
    const int*   ids       = (const int*)  d_in[0];
    const float* emb       = (const float*)d_in[1];
    const float* in_proj_w = (const float*)d_in[2];   // [NL, 2*DI, D]
    const float* conv_w    = (const float*)d_in[3];   // [NL, DI, 4]
    const float* conv_b    = (const float*)d_in[4];   // [NL, DI]
    const float* x_proj_w  = (const float*)d_in[5];   // [NL, 80, DI]
    const float* dt_proj_w = (const float*)d_in[6];   // [NL, DI, 48]
    const float* dt_proj_b = (const float*)d_in[7];   // [NL, DI]
    const float* A_log     = (const float*)d_in[8];   // [NL, DI, 16]
    const float* D_param   = (const float*)d_in[9];   // [NL, DI]
    const float* out_proj_w= (const float*)d_in[10];  // [NL, D, DI]
    const float* norm_w    = (const float*)d_in[11];  // [NL, D]
    const float* norm_f_w  = (const float*)d_in[12];  // [D]
    float* out = (float*)d_out;

    float* s = nullptr;
    cudaGetSymbolAddress((void**)&s, g_scratch);
    float* res = s + OFF_RES;
    float* h   = s + OFF_H;
    float* x   = s + OFF_X;
    float* xz  = s + OFF_XZ;
    float* xc  = s + OFF_XC;
    float* dtl = s + OFF_DT;
    float* y   = s + OFF_Y;
    float* dbl = s + OFF_DBL;
    float* che = s + OFF_CHE;
    float* apr = s + OFF_APR;
    float* pre = s + OFF_PRE;
    float* xwp = s + OFF_XWP;
    float* dwp = s + OFF_DWP;

    constexpr int LD = 36;
    const int smem128 = (2 * 128 * LD + 2 * 128 * LD) * 4;   // 73728
    const int smem64  = (2 * 128 * LD + 2 * 64  * LD) * 4;   // 55296
    cudaFuncSetAttribute(wmma_tn<128>, cudaFuncAttributeMaxDynamicSharedMemorySize, smem128);
    cudaFuncSetAttribute(wmma_tn<64>,  cudaFuncAttributeMaxDynamicSharedMemorySize, smem64);

    // weight padding (deterministic, every launch)
    pad_xw_kernel<<<(NLs * 128 * DIm + 255) / 256, 256>>>(x_proj_w, xwp);
    pad_dw_kernel<<<(NLs * DIm * 64 + 255) / 256, 256>>>(dt_proj_w, dwp);

    embed_kernel<<<(Mrows * Dm + 255) / 256, 256>>>(ids, emb, res);

    for (int i = 0; i < NLs; i++) {
        // h = rms(res += x)
        rms_resid_kernel<<<Mrows, 256>>>(res, x, norm_w + (size_t)i * Dm, h, i > 0);

        // xz = h @ in_proj^T   [2048, 3072], K=768
        {
            dim3 g(2 * DIm / 128, Mrows / 128);
            wmma_tn<128><<<g, 256, smem128>>>(h, Dm, in_proj_w + (size_t)i * 2 * DIm * Dm,
                                              xz, 2 * DIm, Dm);
        }

        // xc = silu(causal depthwise conv(xi) + b)
        conv_silu_kernel<<<(Mrows * DIm + 255) / 256, 256>>>(
            xz, conv_w + (size_t)i * DIm * 4, conv_b + (size_t)i * DIm, xc);

        // dbl = xc @ xw_pad^T   [2048, 128], K=1536  (cols >= 80 are zero)
        {
            dim3 g(128 / 64, Mrows / 128);
            wmma_tn<64><<<g, 256, smem64>>>(xc, DIm, xwp + (size_t)i * 128 * DIm,
                                            dbl, DBL_LD, DIm);
        }

        // dt_lin = dbl[:, :64] @ dw_pad^T   [2048, 1536], K=64
        // (dbl cols 48..63 hold B but dw_pad cols 48..63 are zero -> exact)
        {
            dim3 g(DIm / 128, Mrows / 128);
            wmma_tn<128><<<g, 256, smem128>>>(dbl, DBL_LD, dwp + (size_t)i * DIm * 64,
                                              dtl, DIm, 64);
        }

        // chunked selective scan (softplus+bias applied inline, fp32)
        {
            dim3 g1(DIm * 4 / 128, CH, Bb);
            scan_pass1<<<g1, 128>>>(xc, dtl, dbl, A_log + (size_t)i * DIm * Nst,
                                    dt_proj_b + (size_t)i * DIm, che, apr);
            scan_pass2<<<(Bb * DIm * Nst + 255) / 256, 256>>>(che, apr, pre);
            scan_pass3<<<g1, 128>>>(xc, dtl, dbl, A_log + (size_t)i * DIm * Nst,
                                    dt_proj_b + (size_t)i * DIm,
                                    D_param + (size_t)i * DIm, xz, pre, y);
        }

        // x = y @ out_proj^T   [2048, 768], K=1536
        {
            dim3 g(Dm / 64, Mrows / 128);
            wmma_tn<64><<<g, 256, smem64>>>(y, DIm, out_proj_w + (size_t)i * Dm * DIm,
                                            x, Dm, DIm);
        }
    }

    // final: out = rms(res + x) * norm_f_w
    rms_resid_kernel<<<Mrows, 256>>>(res, x, norm_f_w, out, 1);
}

// round 7
// speedup vs baseline: 6.8524x; 1.6255x over previous
#include <cuda_runtime.h>
#include <cuda_fp16.h>
#include <math.h>
#include <mma.h>

using namespace nvcuda;

// ---------------- model constants ----------------
constexpr int Dm  = 768;
constexpr int DIm = 1536;
constexpr int Nst = 16;
constexpr int NLs = 8;
constexpr int Bb  = 2;
constexpr int Ll  = 1024;
constexpr int Mrows = Bb * Ll;          // 2048
constexpr float EPSf = 1e-5f;
constexpr int CH = 16;                  // scan chunks
constexpr int CL = Ll / CH;             // 64 steps per chunk
constexpr int DBL_LD = 128;             // padded dbl row stride

// ---------------- fp32 scratch ----------------
constexpr size_t OFF_RES = 0;
constexpr size_t OFF_H   = OFF_RES + (size_t)Mrows * Dm;
constexpr size_t OFF_X   = OFF_H   + (size_t)Mrows * Dm;
constexpr size_t OFF_XZ  = OFF_X   + (size_t)Mrows * Dm;
constexpr size_t OFF_XC  = OFF_XZ  + (size_t)Mrows * 2 * DIm;
constexpr size_t OFF_DT  = OFF_XC  + (size_t)Mrows * DIm;       // dt_lin
constexpr size_t OFF_Y   = OFF_DT  + (size_t)Mrows * DIm;
constexpr size_t OFF_DBL = OFF_Y   + (size_t)Mrows * DIm;       // Mrows x 128
constexpr size_t CHSZ    = (size_t)Bb * CH * DIm * Nst;
constexpr size_t OFF_CHE = OFF_DBL + (size_t)Mrows * DBL_LD;
constexpr size_t OFF_APR = OFF_CHE + CHSZ;
constexpr size_t OFF_PRE = OFF_APR + CHSZ;
constexpr size_t SCRATCH_TOTAL = OFF_PRE + CHSZ;

__device__ float g_scratch[SCRATCH_TOTAL];

// ---------------- fp16 weight scratch ----------------
constexpr size_t HSZ_IN  = (size_t)NLs * 2 * DIm * Dm;    // in_proj
constexpr size_t HSZ_OUT = (size_t)NLs * Dm * DIm;        // out_proj
constexpr size_t HSZ_XW  = (size_t)NLs * 128 * DIm;       // x_proj padded N=128
constexpr size_t HSZ_DW  = (size_t)NLs * DIm * 64;        // dt_proj padded K=64
constexpr size_t HOFF_IN  = 0;
constexpr size_t HOFF_OUT = HOFF_IN  + HSZ_IN;
constexpr size_t HOFF_XW  = HOFF_OUT + HSZ_OUT;
constexpr size_t HOFF_DW  = HOFF_XW  + HSZ_XW;
constexpr size_t HTOTAL   = HOFF_DW  + HSZ_DW;

__device__ __half g_wh[HTOTAL];

// ---------------- cp.async helpers ----------------
__device__ __forceinline__ void cp16(void* smem_ptr, const void* gmem_ptr)
{
    unsigned s = (unsigned)__cvta_generic_to_shared(smem_ptr);
    asm volatile("cp.async.cg.shared.global [%0], [%1], 16;\n" :: "r"(s), "l"(gmem_ptr));
}
__device__ __forceinline__ void cp_commit()
{
    asm volatile("cp.async.commit_group;\n" ::: "memory");
}
template <int N>
__device__ __forceinline__ void cp_wait()
{
    asm volatile("cp.async.wait_group %0;\n" :: "n"(N) : "memory");
}

// ---------------- weight conversion / padding (fp32 -> fp16) ----------------
__global__ void conv_w_kernel(const float* __restrict__ src, __half* __restrict__ dst, int n)
{
    int i = blockIdx.x * blockDim.x + threadIdx.x;
    if (i < n) dst[i] = __float2half_rn(src[i]);
}
__global__ void pad_xw_kernel(const float* __restrict__ xw, __half* __restrict__ xwp)
{
    int idx = blockIdx.x * blockDim.x + threadIdx.x;
    if (idx >= NLs * 128 * DIm) return;
    int l = idx / (128 * DIm);
    int rem = idx - l * (128 * DIm);
    int r = rem / DIm;
    int k = rem - r * DIm;
    xwp[idx] = (r < 80) ? __float2half_rn(xw[((size_t)l * 80 + r) * DIm + k]) : __half(0.f);
}
__global__ void pad_dw_kernel(const float* __restrict__ dw, __half* __restrict__ dwp)
{
    int idx = blockIdx.x * blockDim.x + threadIdx.x;
    if (idx >= NLs * DIm * 64) return;
    int l = idx / (DIm * 64);
    int rem = idx - l * (DIm * 64);
    int d = rem / 64;
    int c = rem - d * 64;
    dwp[idx] = (c < 48) ? __float2half_rn(dw[((size_t)l * DIm + d) * 48 + c]) : __half(0.f);
}

// ---------------- embedding gather ----------------
__global__ void embed_kernel(const int* __restrict__ ids,
                             const float* __restrict__ emb,
                             float* __restrict__ res)
{
    int idx = blockIdx.x * blockDim.x + threadIdx.x;
    if (idx >= Mrows * Dm) return;
    int row = idx / Dm;
    int c   = idx - row * Dm;
    res[idx] = emb[(size_t)ids[row] * Dm + c];
}

// ---------------- residual add + RMSNorm ----------------
__global__ void rms_resid_kernel(float* __restrict__ res,
                                 const float* __restrict__ xadd,
                                 const float* __restrict__ w,
                                 float* __restrict__ out,
                                 int addx)
{
    const int row = blockIdx.x;
    const int tid = threadIdx.x;
    float v[3];
    float local = 0.f;
#pragma unroll
    for (int j = 0; j < 3; j++) {
        int c = tid + j * 256;
        float t = res[(size_t)row * Dm + c];
        if (addx) {
            t += xadd[(size_t)row * Dm + c];
            res[(size_t)row * Dm + c] = t;
        }
        v[j] = t;
        local += t * t;
    }
#pragma unroll
    for (int o = 16; o > 0; o >>= 1) local += __shfl_xor_sync(0xffffffffu, local, o);
    __shared__ float warpsum[8];
    __shared__ float sscale;
    if ((tid & 31) == 0) warpsum[tid >> 5] = local;
    __syncthreads();
    if (tid == 0) {
        float t = 0.f;
#pragma unroll
        for (int j = 0; j < 8; j++) t += warpsum[j];
        sscale = rsqrtf(t / (float)Dm + EPSf);
    }
    __syncthreads();
    float sc = sscale;
#pragma unroll
    for (int j = 0; j < 3; j++) {
        int c = tid + j * 256;
        out[(size_t)row * Dm + c] = v[j] * sc * w[c];
    }
}

// ============================================================================
// FP16 tensor-core GEMM, fp32 accumulate.
// C[M,N] = A[M,K](fp32, lda) @ W[N,K]^T(fp16, row stride K).
// BM=128, BN in {128,64}, BK=32.  256 threads = 8 warps (2m x 4n).
// Warp tile 64 x BN/4, wmma m16n16k16.
// A staged via register-prefetch + fp32->fp16 convert; W staged via cp.async.
// Requires: M%128==0, N%BN==0, K%32==0.
// ============================================================================
template <int BN>
__global__ __launch_bounds__(256)
void hgemm_tn(const float* __restrict__ A, int lda,
              const __half* __restrict__ W,
              float* __restrict__ C, int ldc, int K)
{
    constexpr int BM = 128;
    constexpr int BK = 32;
    constexpr int LD = BK + 8;       // 40 halves = 80B rows (16B-aligned)
    constexpr int WM = 64;
    constexpr int WN = BN / 4;
    constexpr int AF = WM / 16;      // 4
    constexpr int BF = WN / 16;      // 2 or 1

    __shared__ __half As[2][BM][LD];
    __shared__ __half Ws[2][BN][LD];

    const int t    = threadIdx.x;
    const int warp = t >> 5;
    const int wm   = (warp & 1) * WM;
    const int wn   = (warp >> 1) * WN;
    const int bm   = blockIdx.y * BM;
    const int bn   = blockIdx.x * BN;

    // A loader: row = t>>1, cols (t&1)*16 + {0,4,8,12}
    const int arow = t >> 1;
    const int ac0  = (t & 1) * 16;
    const float* Ap = A + (size_t)(bm + arow) * lda + ac0;

    // W loader (cp.async 16B = 8 halves)
    int wrow, wc0, wcn;
    if (BN == 128) { wrow = t >> 1; wc0 = (t & 1) * 16; wcn = 2; }
    else           { wrow = t >> 2; wc0 = (t & 3) * 8;  wcn = 1; }
    const __half* Wp = W + (size_t)(bn + wrow) * K + wc0;

    float4 av[4];

    auto loadA = [&](int k0) {
#pragma unroll
        for (int i = 0; i < 4; i++)
            av[i] = *(const float4*)(Ap + k0 + i * 4);
    };
    auto storeA = [&](int stage) {
#pragma unroll
        for (int i = 0; i < 4; i++) {
            __half2 h0 = __floats2half2_rn(av[i].x, av[i].y);
            __half2 h1 = __floats2half2_rn(av[i].z, av[i].w);
            *(__half2*)&As[stage][arow][ac0 + i * 4 + 0] = h0;
            *(__half2*)&As[stage][arow][ac0 + i * 4 + 2] = h1;
        }
    };
    auto issueW = [&](int stage, int k0) {
#pragma unroll
        for (int i = 0; i < 2; i++) {
            if (i < wcn)
                cp16(&Ws[stage][wrow][wc0 + i * 8], Wp + k0 + i * 8);
        }
        cp_commit();
    };

    wmma::fragment<wmma::accumulator, 16, 16, 16, float> acc[AF][BF];
#pragma unroll
    for (int i = 0; i < AF; i++)
#pragma unroll
        for (int j = 0; j < BF; j++)
            wmma::fill_fragment(acc[i][j], 0.f);

    const int nt = K / BK;

    // prologue: stage tile 0
    loadA(0);
    issueW(0, 0);
    storeA(0);
    cp_wait<0>();
    __syncthreads();

    for (int tt = 0; tt < nt; ++tt) {
        const int buf = tt & 1;
        const bool more = (tt + 1 < nt);
        if (more) {
            loadA((tt + 1) * BK);
            issueW(buf ^ 1, (tt + 1) * BK);
        }

#pragma unroll
        for (int kk = 0; kk < BK; kk += 16) {
            wmma::fragment<wmma::matrix_a, 16, 16, 16, __half, wmma::row_major> af[AF];
            wmma::fragment<wmma::matrix_b, 16, 16, 16, __half, wmma::col_major> bf[BF];
#pragma unroll
            for (int i = 0; i < AF; i++)
                wmma::load_matrix_sync(af[i], &As[buf][wm + i * 16][kk], LD);
#pragma unroll
            for (int j = 0; j < BF; j++)
                wmma::load_matrix_sync(bf[j], &Ws[buf][wn + j * 16][kk], LD);
#pragma unroll
            for (int i = 0; i < AF; i++)
#pragma unroll
                for (int j = 0; j < BF; j++)
                    wmma::mma_sync(acc[i][j], af[i], bf[j], acc[i][j]);
        }

        if (more) {
            storeA(buf ^ 1);
            cp_wait<0>();
        }
        __syncthreads();
    }

#pragma unroll
    for (int i = 0; i < AF; i++)
#pragma unroll
        for (int j = 0; j < BF; j++)
            wmma::store_matrix_sync(&C[(size_t)(bm + wm + i * 16) * ldc + bn + wn + j * 16],
                                    acc[i][j], ldc, wmma::mem_row_major);
}

// ---------------- depthwise causal conv (K=4) + SiLU ----------------
__global__ void conv_silu_kernel(const float* __restrict__ xz,
                                 const float* __restrict__ w,
                                 const float* __restrict__ bias,
                                 float* __restrict__ xc)
{
    int idx = blockIdx.x * blockDim.x + threadIdx.x;
    if (idx >= Mrows * DIm) return;
    int row = idx / DIm;
    int c   = idx - row * DIm;
    int l   = row & (Ll - 1);
    float s = bias[c];
#pragma unroll
    for (int k = 0; k < 4; k++) {
        int ll = l - 3 + k;
        if (ll >= 0) s += w[c * 4 + k] * xz[(size_t)(row - 3 + k) * (2 * DIm) + c];
    }
    xc[idx] = s / (1.f + expf(-s));
}

// ============================================================================
// Chunked selective scan (3 phases), 4 lanes per channel, CH chunks of CL.
// ============================================================================
__device__ __forceinline__ float softplus_f(float x)
{
    return (x > 20.f) ? x : log1pf(__expf(x));
}

__global__ void scan_pass1(const float* __restrict__ xc,
                           const float* __restrict__ dtl,
                           const float* __restrict__ dbl,
                           const float* __restrict__ A_log,
                           const float* __restrict__ dtb_bias,
                           float* __restrict__ chk_end,
                           float* __restrict__ aprod)
{
    int gt = blockIdx.x * blockDim.x + threadIdx.x;
    int d = gt >> 2;
    int q = gt & 3;
    int c = blockIdx.y;
    int b = blockIdx.z;
    if (d >= DIm) return;

    float Ac[4], st[4] = {0.f, 0.f, 0.f, 0.f}, ap[4] = {1.f, 1.f, 1.f, 1.f};
#pragma unroll
    for (int n = 0; n < 4; n++)
        Ac[n] = -expf(A_log[(size_t)d * 16 + q * 4 + n]);
    const float db = dtb_bias[d];

    const int l0 = c * CL;
    const float* xcb = xc  + ((size_t)b * Ll + l0) * DIm + d;
    const float* dtb = dtl + ((size_t)b * Ll + l0) * DIm + d;
    const float* blb = dbl + ((size_t)b * Ll + l0) * DBL_LD + 48 + q * 4;

    for (int l = 0; l < CL; l++) {
        float u   = xcb[(size_t)l * DIm];
        float dtt = softplus_f(dtb[(size_t)l * DIm] + db);
        float du  = dtt * u;
        const float* bl = blb + (size_t)l * DBL_LD;
#pragma unroll
        for (int n = 0; n < 4; n++) {
            float e = __expf(dtt * Ac[n]);
            st[n] = fmaf(e, st[n], du * bl[n]);
            ap[n] *= e;
        }
    }
    size_t base = (((size_t)b * CH + c) * DIm + d) * 16 + q * 4;
#pragma unroll
    for (int n = 0; n < 4; n++) {
        chk_end[base + n] = st[n];
        aprod[base + n]   = ap[n];
    }
}

__global__ void scan_pass2(const float* __restrict__ chk_end,
                           const float* __restrict__ aprod,
                           float* __restrict__ chk_pref)
{
    int idx = blockIdx.x * blockDim.x + threadIdx.x;
    if (idx >= Bb * DIm * Nst) return;
    int b = idx / (DIm * Nst);
    int r = idx - b * (DIm * Nst);
    float hv = 0.f;
#pragma unroll
    for (int c = 0; c < CH; c++) {
        size_t o = ((size_t)b * CH + c) * DIm * Nst + r;
        chk_pref[o] = hv;
        hv = fmaf(aprod[o], hv, chk_end[o]);
    }
}

__global__ void scan_pass3(const float* __restrict__ xc,
                           const float* __restrict__ dtl,
                           const float* __restrict__ dbl,
                           const float* __restrict__ A_log,
                           const float* __restrict__ dtb_bias,
                           const float* __restrict__ Dp,
                           const float* __restrict__ xz,
                           const float* __restrict__ chk_pref,
                           float* __restrict__ y)
{
    int gt = blockIdx.x * blockDim.x + threadIdx.x;
    int d = gt >> 2;
    int q = gt & 3;
    int c = blockIdx.y;
    int b = blockIdx.z;
    if (d >= DIm) return;

    float Ac[4], st[4];
#pragma unroll
    for (int n = 0; n < 4; n++)
        Ac[n] = -expf(A_log[(size_t)d * 16 + q * 4 + n]);
    {
        size_t base = (((size_t)b * CH + c) * DIm + d) * 16 + q * 4;
#pragma unroll
        for (int n = 0; n < 4; n++) st[n] = chk_pref[base + n];
    }
    const float db = dtb_bias[d];
    float dp = Dp[d];

    const int l0 = c * CL;
    const float* xcb = xc  + ((size_t)b * Ll + l0) * DIm + d;
    const float* dtb = dtl + ((size_t)b * Ll + l0) * DIm + d;
    const float* zb  = xz  + ((size_t)b * Ll + l0) * (2 * DIm) + DIm + d;
    const float* blb = dbl + ((size_t)b * Ll + l0) * DBL_LD + 48 + q * 4;
    float*       yb  = y   + ((size_t)b * Ll + l0) * DIm + d;

    for (int l = 0; l < CL; l++) {
        float u   = xcb[(size_t)l * DIm];
        float dtt = softplus_f(dtb[(size_t)l * DIm] + db);
        float du  = dtt * u;
        const float* bl = blb + (size_t)l * DBL_LD;
        float yv = 0.f;
#pragma unroll
        for (int n = 0; n < 4; n++) {
            float e = __expf(dtt * Ac[n]);
            st[n] = fmaf(e, st[n], du * bl[n]);
            yv = fmaf(st[n], bl[16 + n], yv);
        }
        yv += __shfl_xor_sync(0xffffffffu, yv, 1);
        yv += __shfl_xor_sync(0xffffffffu, yv, 2);
        if (q == 0) {
            float z = zb[(size_t)l * (2 * DIm)];
            yv = fmaf(u, dp, yv);
            yb[(size_t)l * DIm] = yv * (z / (1.f + __expf(-z)));
        }
    }
}

// ---------------- host launcher ----------------
extern "C" void kernel_launch(void* const* d_in, const int* in_sizes, int n_in,
                              void* d_out, int out_size)
{
    const int*   ids       = (const int*)  d_in[0];
    const float* emb       = (const float*)d_in[1];
    const float* in_proj_w = (const float*)d_in[2];   // [NL, 2*DI, D]
    const float* conv_w    = (const float*)d_in[3];   // [NL, DI, 4]
    const float* conv_b    = (const float*)d_in[4];   // [NL, DI]
    const float* x_proj_w  = (const float*)d_in[5];   // [NL, 80, DI]
    const float* dt_proj_w = (const float*)d_in[6];   // [NL, DI, 48]
    const float* dt_proj_b = (const float*)d_in[7];   // [NL, DI]
    const float* A_log     = (const float*)d_in[8];   // [NL, DI, 16]
    const float* D_param   = (const float*)d_in[9];   // [NL, DI]
    const float* out_proj_w= (const float*)d_in[10];  // [NL, D, DI]
    const float* norm_w    = (const float*)d_in[11];  // [NL, D]
    const float* norm_f_w  = (const float*)d_in[12];  // [D]
    float* out = (float*)d_out;

    float* s = nullptr;
    cudaGetSymbolAddress((void**)&s, g_scratch);
    __half* wh = nullptr;
    cudaGetSymbolAddress((void**)&wh, g_wh);

    float* res = s + OFF_RES;
    float* h   = s + OFF_H;
    float* x   = s + OFF_X;
    float* xz  = s + OFF_XZ;
    float* xc  = s + OFF_XC;
    float* dtl = s + OFF_DT;
    float* y   = s + OFF_Y;
    float* dbl = s + OFF_DBL;
    float* che = s + OFF_CHE;
    float* apr = s + OFF_APR;
    float* pre = s + OFF_PRE;

    __half* w_in  = wh + HOFF_IN;
    __half* w_out = wh + HOFF_OUT;
    __half* w_xw  = wh + HOFF_XW;
    __half* w_dw  = wh + HOFF_DW;

    // weight conversion / padding (deterministic, every launch)
    conv_w_kernel<<<((int)HSZ_IN  + 255) / 256, 256>>>(in_proj_w,  w_in,  (int)HSZ_IN);
    conv_w_kernel<<<((int)HSZ_OUT + 255) / 256, 256>>>(out_proj_w, w_out, (int)HSZ_OUT);
    pad_xw_kernel<<<((int)HSZ_XW + 255) / 256, 256>>>(x_proj_w, w_xw);
    pad_dw_kernel<<<((int)HSZ_DW + 255) / 256, 256>>>(dt_proj_w, w_dw);

    embed_kernel<<<(Mrows * Dm + 255) / 256, 256>>>(ids, emb, res);

    for (int i = 0; i < NLs; i++) {
        // h = rms(res += x)
        rms_resid_kernel<<<Mrows, 256>>>(res, x, norm_w + (size_t)i * Dm, h, i > 0);

        // xz = h @ in_proj^T   [2048, 3072], K=768
        {
            dim3 g(2 * DIm / 128, Mrows / 128);
            hgemm_tn<128><<<g, 256>>>(h, Dm, w_in + (size_t)i * 2 * DIm * Dm,
                                      xz, 2 * DIm, Dm);
        }

        // xc = silu(causal depthwise conv(xi) + b)
        conv_silu_kernel<<<(Mrows * DIm + 255) / 256, 256>>>(
            xz, conv_w + (size_t)i * DIm * 4, conv_b + (size_t)i * DIm, xc);

        // dbl = xc @ xw_pad^T   [2048, 128], K=1536
        {
            dim3 g(128 / 64, Mrows / 128);
            hgemm_tn<64><<<g, 256>>>(xc, DIm, w_xw + (size_t)i * 128 * DIm,
                                     dbl, DBL_LD, DIm);
        }

        // dt_lin = dbl[:, :64] @ dw_pad^T   [2048, 1536], K=64
        {
            dim3 g(DIm / 128, Mrows / 128);
            hgemm_tn<128><<<g, 256>>>(dbl, DBL_LD, w_dw + (size_t)i * DIm * 64,
                                      dtl, DIm, 64);
        }

        // chunked selective scan
        {
            dim3 g1(DIm * 4 / 128, CH, Bb);
            scan_pass1<<<g1, 128>>>(xc, dtl, dbl, A_log + (size_t)i * DIm * Nst,
                                    dt_proj_b + (size_t)i * DIm, che, apr);
            scan_pass2<<<(Bb * DIm * Nst + 255) / 256, 256>>>(che, apr, pre);
            scan_pass3<<<g1, 128>>>(xc, dtl, dbl, A_log + (size_t)i * DIm * Nst,
                                    dt_proj_b + (size_t)i * DIm,
                                    D_param + (size_t)i * DIm, xz, pre, y);
        }

        // x = y @ out_proj^T   [2048, 768], K=1536
        {
            dim3 g(Dm / 64, Mrows / 128);
            hgemm_tn<64><<<g, 256>>>(y, DIm, w_out + (size_t)i * Dm * DIm,
                                     x, Dm, DIm);
        }
    }

    // final: out = rms(res + x) * norm_f_w
    rms_resid_kernel<<<Mrows, 256>>>(res, x, norm_f_w, out, 1);
}